// round 8
// baseline (speedup 1.0000x reference)
#include <cuda_runtime.h>
#include <cuda_fp16.h>
#include <cstdint>

#define B_  4
#define S_  2048
#define D_  1024
#define H_  16
#define M_TOT 8192

// ---------------- device scratch (no allocs allowed) ----------------
__device__ __align__(256) __half g_qh[M_TOT * D_], g_ql[M_TOT * D_];
__device__ __align__(256) __half g_kh[M_TOT * D_], g_kl[M_TOT * D_];
__device__ __align__(256) __half g_vh[M_TOT * D_], g_vl[M_TOT * D_];
__device__ __align__(256) __half g_wqh[H_ * 64 * D_], g_wql[H_ * 64 * D_];
__device__ __align__(256) __half g_wkh[H_ * 64 * D_], g_wkl[H_ * 64 * D_];
__device__ __align__(256) __half g_wvh[H_ * 64 * D_], g_wvl[H_ * 64 * D_];
__device__ __align__(256) __half g_woh[D_ * D_],     g_wol[D_ * D_];
__device__ __align__(256) __half g_Qh[64 * S_ * 64],  g_Ql[64 * S_ * 64];   // [bh][s][dk] (pre-scaled)
__device__ __align__(256) __half g_Kh[64 * S_ * 64],  g_Kl[64 * S_ * 64];   // [bh][key][dk]
__device__ __align__(256) __half g_Vth[64 * 64 * S_], g_Vtl[64 * 64 * S_];  // [bh][dv][key]
__device__ __align__(256) __half g_Hh[M_TOT * D_], g_Hl[M_TOT * D_];

// ---------------- PTX helpers (baseline ISA: sm_80+) ----------------
__device__ __forceinline__ uint32_t smem_u32(const void* p) {
    uint32_t a;
    asm("{ .reg .u64 t; cvta.to.shared.u64 t, %1; cvt.u32.u64 %0, t; }"
        : "=r"(a) : "l"(p));
    return a;
}
__device__ __forceinline__ void cp16(uint32_t dst, const void* src) {
    asm volatile("cp.async.cg.shared.global [%0], [%1], 16;"
                 :: "r"(dst), "l"(src) : "memory");
}
#define CP_COMMIT() asm volatile("cp.async.commit_group;" ::: "memory")
#define CP_WAIT1()  asm volatile("cp.async.wait_group 1;"  ::: "memory")
#define CP_WAIT0()  asm volatile("cp.async.wait_group 0;"  ::: "memory")

__device__ __forceinline__ void ldsm_x4(uint32_t* r, uint32_t addr) {
    asm volatile("ldmatrix.sync.aligned.m8n8.x4.shared.b16 {%0,%1,%2,%3}, [%4];"
                 : "=r"(r[0]), "=r"(r[1]), "=r"(r[2]), "=r"(r[3]) : "r"(addr));
}
// fp16 inputs, fp32 accumulate
__device__ __forceinline__ void hmma(float* d, const uint32_t* a,
                                     uint32_t b0, uint32_t b1) {
    asm volatile("mma.sync.aligned.m16n8k16.row.col.f32.f16.f16.f32 "
                 "{%0,%1,%2,%3}, {%4,%5,%6,%7}, {%8,%9}, {%0,%1,%2,%3};"
                 : "+f"(d[0]), "+f"(d[1]), "+f"(d[2]), "+f"(d[3])
                 : "r"(a[0]), "r"(a[1]), "r"(a[2]), "r"(a[3]), "r"(b0), "r"(b1));
}
// fp16 inputs, fp16 accumulate (packed 2x half per reg)
__device__ __forceinline__ void hmma16(uint32_t* d, const uint32_t* a,
                                       uint32_t b0, uint32_t b1) {
    asm volatile("mma.sync.aligned.m16n8k16.row.col.f16.f16.f16.f16 "
                 "{%0,%1}, {%2,%3,%4,%5}, {%6,%7}, {%0,%1};"
                 : "+r"(d[0]), "+r"(d[1])
                 : "r"(a[0]), "r"(a[1]), "r"(a[2]), "r"(a[3]), "r"(b0), "r"(b1));
}
__device__ __forceinline__ uint32_t swz(uint32_t off) {
    return off ^ ((off >> 3) & 0x70);
}
__device__ __forceinline__ void split_f16(float x, __half& h, __half& l) {
    h = __float2half_rn(x);
    l = __float2half_rn(x - __half2float(h));
}
__device__ __forceinline__ uint32_t packsplit(float x, float y, uint32_t& lo) {
    __half hx, hy, lx, ly;
    split_f16(x, hx, lx);
    split_f16(y, hy, ly);
    __half2 hv = __halves2half2(hx, hy);
    __half2 lv = __halves2half2(lx, ly);
    lo = *reinterpret_cast<uint32_t*>(&lv);
    return *reinterpret_cast<uint32_t*>(&hv);
}

// ---------------- conversion kernels (fused) ----------------
__global__ __launch_bounds__(256) void conv_in3(const float* __restrict__ q,
                                                const float* __restrict__ k,
                                                const float* __restrict__ v)
{
    const int which = blockIdx.y;
    const float* x = (which == 0) ? q : ((which == 1) ? k : v);
    __half* hi = (which == 0) ? g_qh : ((which == 1) ? g_kh : g_vh);
    __half* lo = (which == 0) ? g_ql : ((which == 1) ? g_kl : g_vl);
    size_t i = ((size_t)blockIdx.x * 256 + threadIdx.x) * 4;
    float4 vv = *reinterpret_cast<const float4*>(x + i);
    __half h0, h1, h2, h3, l0, l1, l2, l3;
    split_f16(vv.x, h0, l0); split_f16(vv.y, h1, l1);
    split_f16(vv.z, h2, l2); split_f16(vv.w, h3, l3);
    *reinterpret_cast<__half2*>(hi + i)     = __halves2half2(h0, h1);
    *reinterpret_cast<__half2*>(hi + i + 2) = __halves2half2(h2, h3);
    *reinterpret_cast<__half2*>(lo + i)     = __halves2half2(l0, l1);
    *reinterpret_cast<__half2*>(lo + i + 2) = __halves2half2(l2, l3);
}

// W[h][k][n] (16,1024,64) -> Wt[h][n][k] hi/lo, all three weights
__global__ __launch_bounds__(256) void conv_w3(const float* __restrict__ Wq,
                                               const float* __restrict__ Wk,
                                               const float* __restrict__ Wv)
{
    const int which = blockIdx.y;
    const float* W = (which == 0) ? Wq : ((which == 1) ? Wk : Wv);
    __half* hi = (which == 0) ? g_wqh : ((which == 1) ? g_wkh : g_wvh);
    __half* lo = (which == 0) ? g_wql : ((which == 1) ? g_wkl : g_wvl);
    int idx = blockIdx.x * 256 + threadIdx.x;        // h*65536 + n*1024 + k
    int k = idx & 1023;
    int n = (idx >> 10) & 63;
    int h = idx >> 16;
    float x = W[((size_t)h * D_ + k) * 64 + n];
    __half hh, ll;
    split_f16(x, hh, ll);
    hi[idx] = hh; lo[idx] = ll;
}

__global__ __launch_bounds__(256) void conv_wo(const float* __restrict__ Wo)
{
    int idx = blockIdx.x * 256 + threadIdx.x;        // n*1024 + k
    int k = idx & 1023;
    int n = idx >> 10;
    float x = Wo[(size_t)k * D_ + n];
    __half hh, ll;
    split_f16(x, hh, ll);
    g_woh[idx] = hh; g_wol[idx] = ll;
}

// ---------------- split-fp16 HMMA GEMM (256 thr, 8 warps x 16 rows) ----------------
// hh term: f32 accumulate. Cross terms (hi*lo + lo*hi): fp16 accumulate
// (cross magnitude ~2^-11 of result -> fp16 accum error ~2^-22 of result).
// mode 0/1/2: Q/K/V projection epilogues; mode 3: fp32 out; mode 4: z-merged projections.
#define STAGE_BYTES 49152
#define A_HI_OFF 0
#define A_LO_OFF 16384
#define B_HI_OFF 32768
#define B_LO_OFF 40960
#define MMA_SMEM (2 * STAGE_BYTES)

__global__ __launch_bounds__(256) void mma_gemm(const __half* __restrict__ ah_,
                                                const __half* __restrict__ al_,
                                                const __half* __restrict__ bh_,
                                                const __half* __restrict__ bl_,
                                                float* __restrict__ outp, int mode)
{
    extern __shared__ char sm[];
    const uint32_t smem = smem_u32(sm);
    const int tid  = threadIdx.x;
    const int wid  = tid >> 5;
    const int lane = tid & 31;
    const int nb   = blockIdx.x;
    const int m0   = blockIdx.y * 128;
    const int mbase = wid * 16;

    int emode = mode;
    const __half *ah = ah_, *al = al_, *bh = bh_, *bl = bl_;
    if (mode == 4) {
        const int z = blockIdx.z;          // 0=Q 1=K 2=V
        emode = z;
        ah = (z == 0) ? g_qh : ((z == 1) ? g_kh : g_vh);
        al = (z == 0) ? g_ql : ((z == 1) ? g_kl : g_vl);
        bh = (z == 0) ? g_wqh : ((z == 1) ? g_wkh : g_wvh);
        bl = (z == 0) ? g_wql : ((z == 1) ? g_wkl : g_wvl);
    }

    const __half* aH = ah + (size_t)m0 * D_;
    const __half* aL = al + (size_t)m0 * D_;
    const __half* bH = bh + (size_t)nb * 64 * D_;
    const __half* bL = bl + (size_t)nb * 64 * D_;

    const int arow = tid >> 1, ahalf = tid & 1;
    const int brow_ = tid >> 2, bq = tid & 3;
    auto load_stage = [&](int c, int buf) {
        const uint32_t sb = smem + buf * STAGE_BYTES;
        const int k0 = c * 64;
        const char* gh = (const char*)(aH + (size_t)arow * D_ + k0) + ahalf * 64;
        const char* gl = (const char*)(aL + (size_t)arow * D_ + k0) + ahalf * 64;
        #pragma unroll
        for (int j = 0; j < 4; ++j) {
            uint32_t sw = swz(arow * 128 + ahalf * 64 + j * 16);
            cp16(sb + A_HI_OFF + sw, gh + j * 16);
            cp16(sb + A_LO_OFF + sw, gl + j * 16);
        }
        const char* gbh = (const char*)(bH + (size_t)brow_ * D_ + k0) + bq * 32;
        const char* gbl = (const char*)(bL + (size_t)brow_ * D_ + k0) + bq * 32;
        #pragma unroll
        for (int j = 0; j < 2; ++j) {
            uint32_t sw = swz(brow_ * 128 + bq * 32 + j * 16);
            cp16(sb + B_HI_OFF + sw, gbh + j * 16);
            cp16(sb + B_LO_OFF + sw, gbl + j * 16);
        }
    };

    float acc[8][4] = {};
    uint32_t cross[8][2];
    #pragma unroll
    for (int nf = 0; nf < 8; ++nf) { cross[nf][0] = 0u; cross[nf][1] = 0u; }

    load_stage(0, 0);
    CP_COMMIT();

    for (int c = 0; c < 16; ++c) {
        const int buf = c & 1;
        if (c < 15) { load_stage(c + 1, buf ^ 1); CP_COMMIT(); }
        if (c < 15) CP_WAIT1(); else CP_WAIT0();
        __syncthreads();

        const uint32_t sb = smem + buf * STAGE_BYTES;
        #pragma unroll
        for (int ks = 0; ks < 4; ++ks) {
            const int kb = ks * 32;
            uint32_t ahi[4], alo[4];
            {
                uint32_t off = (uint32_t)(mbase + (lane & 15)) * 128
                             + kb + (lane >> 4) * 16;
                uint32_t sw = swz(off);
                ldsm_x4(ahi, sb + A_HI_OFF + sw);
                ldsm_x4(alo, sb + A_LO_OFF + sw);
            }
            uint32_t bhi[4][4], blo[4][4];
            #pragma unroll
            for (int np = 0; np < 4; ++np) {
                uint32_t n  = np * 16 + (lane & 7) + ((lane >> 4) << 3);
                uint32_t off = n * 128 + kb + ((lane >> 3) & 1) * 16;
                uint32_t sw = swz(off);
                ldsm_x4(bhi[np], sb + B_HI_OFF + sw);
                ldsm_x4(blo[np], sb + B_LO_OFF + sw);
            }
            // hh: f32 accumulate (term-major, dep gap 8)
            #pragma unroll
            for (int nf = 0; nf < 8; ++nf) {
                const int np = nf >> 1, sel = (nf & 1) * 2;
                hmma(acc[nf], ahi, bhi[np][sel], bhi[np][sel + 1]);
            }
            // cross: fp16 accumulate
            #pragma unroll
            for (int nf = 0; nf < 8; ++nf) {
                const int np = nf >> 1, sel = (nf & 1) * 2;
                hmma16(cross[nf], ahi, blo[np][sel], blo[np][sel + 1]);
            }
            #pragma unroll
            for (int nf = 0; nf < 8; ++nf) {
                const int np = nf >> 1, sel = (nf & 1) * 2;
                hmma16(cross[nf], alo, bhi[np][sel], bhi[np][sel + 1]);
            }
        }
        __syncthreads();
    }

    // merge fp16 cross accumulators into f32
    #pragma unroll
    for (int nf = 0; nf < 8; ++nf) {
        float2 c01 = __half22float2(*reinterpret_cast<__half2*>(&cross[nf][0]));
        float2 c23 = __half22float2(*reinterpret_cast<__half2*>(&cross[nf][1]));
        acc[nf][0] += c01.x; acc[nf][1] += c01.y;
        acc[nf][2] += c23.x; acc[nf][3] += c23.y;
    }

    // ---- epilogue ----
    const int g = lane >> 2;
    const int t = lane & 3;
    #pragma unroll
    for (int half = 0; half < 2; ++half) {
        const int m = m0 + mbase + half * 8 + g;
        if (emode == 3) {
            float* orow = outp + (size_t)m * D_ + nb * 64;
            #pragma unroll
            for (int nf = 0; nf < 8; ++nf)
                *reinterpret_cast<float2*>(orow + nf * 8 + t * 2) =
                    make_float2(acc[nf][half * 2], acc[nf][half * 2 + 1]);
        } else {
            const int b = m >> 11, s = m & (S_ - 1);
            const int bh_i = b * H_ + nb;
            if (emode < 2) {
                const float sc = (emode == 0) ? 0.125f : 1.0f;
                __half* dh = (emode == 0) ? g_Qh : g_Kh;
                __half* dl = (emode == 0) ? g_Ql : g_Kl;
                size_t base = ((size_t)bh_i * S_ + s) * 64;
                #pragma unroll
                for (int nf = 0; nf < 8; ++nf) {
                    uint32_t lo, hi = packsplit(acc[nf][half * 2] * sc,
                                                acc[nf][half * 2 + 1] * sc, lo);
                    *reinterpret_cast<uint32_t*>(dh + base + nf * 8 + t * 2) = hi;
                    *reinterpret_cast<uint32_t*>(dl + base + nf * 8 + t * 2) = lo;
                }
            } else {
                #pragma unroll
                for (int nf = 0; nf < 8; ++nf) {
                    #pragma unroll
                    for (int e = 0; e < 2; ++e) {
                        int dv = nf * 8 + t * 2 + e;
                        __half hh, ll;
                        split_f16(acc[nf][half * 2 + e], hh, ll);
                        size_t addr = ((size_t)bh_i * 64 + dv) * S_ + s;
                        g_Vth[addr] = hh;
                        g_Vtl[addr] = ll;
                    }
                }
            }
        }
    }
}

// ---------------- tensor-core flash attention (256 thr, 8 warps x 16 q-rows) ----------------
#define KH_OFF 0
#define KL_OFF 8192
#define VH_OFF 16384
#define VL_OFF 24576
#define AT_STAGE 32768
#define QH_OFF 65536
#define QL_OFF (65536 + 16384)
#define ATT_SMEM 98304

__global__ __launch_bounds__(256) void attn_mma()
{
    extern __shared__ char sm[];
    const uint32_t smem = smem_u32(sm);
    const int tid  = threadIdx.x;
    const int wid  = tid >> 5;
    const int lane = tid & 31;
    const int bh   = blockIdx.y;
    const int q0   = blockIdx.x * 128;
    const int mbase = wid * 16;

    // Q tile async load
    {
        const int row = tid >> 1, half = tid & 1;
        const char* gh = (const char*)(g_Qh + ((size_t)bh * S_ + q0 + row) * 64) + half * 64;
        const char* gl = (const char*)(g_Ql + ((size_t)bh * S_ + q0 + row) * 64) + half * 64;
        #pragma unroll
        for (int i = 0; i < 4; ++i) {
            uint32_t sw = swz(row * 128 + half * 64 + i * 16);
            cp16(smem + QH_OFF + sw, gh + i * 16);
            cp16(smem + QL_OFF + sw, gl + i * 16);
        }
    }
    const int r4 = tid >> 2, qq = tid & 3;
    auto load_stage = [&](int kt, int buf) {
        const uint32_t sb = smem + buf * AT_STAGE;
        const char* kh = (const char*)(g_Kh + ((size_t)bh * S_ + kt + r4) * 64) + qq * 32;
        const char* kl = (const char*)(g_Kl + ((size_t)bh * S_ + kt + r4) * 64) + qq * 32;
        const char* vh = (const char*)(g_Vth + ((size_t)bh * 64 + r4) * S_ + kt) + qq * 32;
        const char* vl = (const char*)(g_Vtl + ((size_t)bh * 64 + r4) * S_ + kt) + qq * 32;
        #pragma unroll
        for (int j = 0; j < 2; ++j) {
            uint32_t sw = swz(r4 * 128 + qq * 32 + j * 16);
            cp16(sb + KH_OFF + sw, kh + j * 16);
            cp16(sb + KL_OFF + sw, kl + j * 16);
            cp16(sb + VH_OFF + sw, vh + j * 16);
            cp16(sb + VL_OFF + sw, vl + j * 16);
        }
    };
    load_stage(0, 0);  CP_COMMIT();
    load_stage(64, 1); CP_COMMIT();
    CP_WAIT1();
    __syncthreads();

    // persistent Q hi fragments; Q lo re-loaded per use
    uint32_t qh[4][4];
    #pragma unroll
    for (int ks = 0; ks < 4; ++ks) {
        uint32_t off = (uint32_t)(mbase + (lane & 15)) * 128
                     + ks * 32 + (lane >> 4) * 16;
        ldsm_x4(qh[ks], smem + QH_OFF + swz(off));
    }

    float O[8][4] = {};
    float mrow[2] = {-1e30f, -1e30f};
    float lrow[2] = {};

    for (int c = 0; c < 32; ++c) {
        const uint32_t sb = smem + (c & 1) * AT_STAGE;

        // ---- QK^T (3-MMA split, term-major in np-pairs) ----
        float s[8][4] = {};
        #pragma unroll
        for (int ks = 0; ks < 4; ++ks) {
            uint32_t ql_[4];
            {
                uint32_t off = (uint32_t)(mbase + (lane & 15)) * 128
                             + ks * 32 + (lane >> 4) * 16;
                ldsm_x4(ql_, smem + QL_OFF + swz(off));
            }
            #pragma unroll
            for (int np2 = 0; np2 < 2; ++np2) {
                uint32_t kbh2[2][4], kbl2[2][4];
                #pragma unroll
                for (int j = 0; j < 2; ++j) {
                    const int np = np2 * 2 + j;
                    uint32_t n  = np * 16 + (lane & 7) + ((lane >> 4) << 3);
                    uint32_t off = n * 128 + ks * 32 + ((lane >> 3) & 1) * 16;
                    uint32_t sw = swz(off);
                    ldsm_x4(kbh2[j], sb + KH_OFF + sw);
                    ldsm_x4(kbl2[j], sb + KL_OFF + sw);
                }
                #pragma unroll
                for (int j = 0; j < 4; ++j) {
                    const int p = j >> 1, sel = (j & 1) * 2;
                    hmma(s[np2 * 4 + j], qh[ks], kbh2[p][sel], kbh2[p][sel + 1]);
                }
                #pragma unroll
                for (int j = 0; j < 4; ++j) {
                    const int p = j >> 1, sel = (j & 1) * 2;
                    hmma(s[np2 * 4 + j], qh[ks], kbl2[p][sel], kbl2[p][sel + 1]);
                }
                #pragma unroll
                for (int j = 0; j < 4; ++j) {
                    const int p = j >> 1, sel = (j & 1) * 2;
                    hmma(s[np2 * 4 + j], ql_, kbh2[p][sel], kbh2[p][sel + 1]);
                }
            }
        }

        // ---- online softmax on fragments ----
        #pragma unroll
        for (int half = 0; half < 2; ++half) {
            float rmax = -1e30f;
            #pragma unroll
            for (int nf = 0; nf < 8; ++nf)
                rmax = fmaxf(rmax, fmaxf(s[nf][half * 2], s[nf][half * 2 + 1]));
            rmax = fmaxf(rmax, __shfl_xor_sync(0xffffffffu, rmax, 1));
            rmax = fmaxf(rmax, __shfl_xor_sync(0xffffffffu, rmax, 2));
            const float mnew = fmaxf(mrow[half], rmax);
            const float corr = __expf(mrow[half] - mnew);
            float rsum = 0.0f;
            #pragma unroll
            for (int nf = 0; nf < 8; ++nf) {
                float p0 = __expf(s[nf][half * 2]     - mnew);
                float p1 = __expf(s[nf][half * 2 + 1] - mnew);
                s[nf][half * 2]     = p0;
                s[nf][half * 2 + 1] = p1;
                rsum += p0 + p1;
            }
            rsum += __shfl_xor_sync(0xffffffffu, rsum, 1);
            rsum += __shfl_xor_sync(0xffffffffu, rsum, 2);
            lrow[half] = lrow[half] * corr + rsum;
            mrow[half] = mnew;
            #pragma unroll
            for (int nf = 0; nf < 8; ++nf) {
                O[nf][half * 2]     *= corr;
                O[nf][half * 2 + 1] *= corr;
            }
        }

        // ---- P @ V (3-MMA split, term-major in np-pairs) ----
        #pragma unroll
        for (int kk = 0; kk < 4; ++kk) {
            uint32_t pah[4], pal[4];
            pah[0] = packsplit(s[2 * kk][0],     s[2 * kk][1],     pal[0]);
            pah[1] = packsplit(s[2 * kk][2],     s[2 * kk][3],     pal[1]);
            pah[2] = packsplit(s[2 * kk + 1][0], s[2 * kk + 1][1], pal[2]);
            pah[3] = packsplit(s[2 * kk + 1][2], s[2 * kk + 1][3], pal[3]);
            #pragma unroll
            for (int np2 = 0; np2 < 2; ++np2) {
                uint32_t vbh2[2][4], vbl2[2][4];
                #pragma unroll
                for (int j = 0; j < 2; ++j) {
                    const int np = np2 * 2 + j;
                    uint32_t n  = np * 16 + (lane & 7) + ((lane >> 4) << 3);
                    uint32_t off = n * 128 + kk * 32 + ((lane >> 3) & 1) * 16;
                    uint32_t sw = swz(off);
                    ldsm_x4(vbh2[j], sb + VH_OFF + sw);
                    ldsm_x4(vbl2[j], sb + VL_OFF + sw);
                }
                #pragma unroll
                for (int j = 0; j < 4; ++j) {
                    const int p = j >> 1, sel = (j & 1) * 2;
                    hmma(O[np2 * 4 + j], pah, vbh2[p][sel], vbh2[p][sel + 1]);
                }
                #pragma unroll
                for (int j = 0; j < 4; ++j) {
                    const int p = j >> 1, sel = (j & 1) * 2;
                    hmma(O[np2 * 4 + j], pal, vbh2[p][sel], vbh2[p][sel + 1]);
                }
                #pragma unroll
                for (int j = 0; j < 4; ++j) {
                    const int p = j >> 1, sel = (j & 1) * 2;
                    hmma(O[np2 * 4 + j], pah, vbl2[p][sel], vbl2[p][sel + 1]);
                }
            }
        }

        __syncthreads();
        if (c + 2 < 32) {
            load_stage((c + 2) * 64, c & 1);
            CP_COMMIT();
            CP_WAIT1();
        } else if (c + 1 < 32) {
            CP_WAIT0();
        }
        __syncthreads();
    }

    // ---- epilogue: normalize, split hi/lo, concat-head layout ----
    const int b = bh >> 4, h = bh & 15;
    const int g = lane >> 2, t = lane & 3;
    #pragma unroll
    for (int half = 0; half < 2; ++half) {
        const float inv = 1.0f / lrow[half];
        const int srow = q0 + mbase + half * 8 + g;
        size_t base = ((size_t)(b * S_ + srow)) * D_ + h * 64;
        #pragma unroll
        for (int nf = 0; nf < 8; ++nf) {
            uint32_t lo, hi = packsplit(O[nf][half * 2] * inv,
                                        O[nf][half * 2 + 1] * inv, lo);
            *reinterpret_cast<uint32_t*>(g_Hh + base + nf * 8 + t * 2) = hi;
            *reinterpret_cast<uint32_t*>(g_Hl + base + nf * 8 + t * 2) = lo;
        }
    }
}

// ---------------- launch ----------------
extern "C" void kernel_launch(void* const* d_in, const int* in_sizes, int n_in,
                              void* d_out, int out_size)
{
    const float* q  = (const float*)d_in[0];
    const float* k  = (const float*)d_in[1];
    const float* v  = (const float*)d_in[2];
    const float* Wq = (const float*)d_in[3];
    const float* Wk = (const float*)d_in[4];
    const float* Wv = (const float*)d_in[5];
    const float* Wo = (const float*)d_in[6];
    float* out = (float*)d_out;

    static bool configured = false;
    if (!configured) {
        cudaFuncSetAttribute(mma_gemm, cudaFuncAttributeMaxDynamicSharedMemorySize, MMA_SMEM);
        cudaFuncSetAttribute(attn_mma, cudaFuncAttributeMaxDynamicSharedMemorySize, ATT_SMEM);
        configured = true;
    }

    __half *woh, *wol, *Hh, *Hl;
    cudaGetSymbolAddress((void**)&woh, g_woh); cudaGetSymbolAddress((void**)&wol, g_wol);
    cudaGetSymbolAddress((void**)&Hh, g_Hh);   cudaGetSymbolAddress((void**)&Hl, g_Hl);

    conv_in3<<<dim3(8192, 3), 256>>>(q, k, v);
    conv_w3<<<dim3(4096, 3), 256>>>(Wq, Wk, Wv);
    conv_wo<<<4096, 256>>>(Wo);

    // merged Q/K/V projections: one launch, z = which
    dim3 proj_grid(H_, M_TOT / 128, 3);
    mma_gemm<<<proj_grid, 256, MMA_SMEM>>>(nullptr, nullptr, nullptr, nullptr, nullptr, 4);

    dim3 attn_grid(S_ / 128, B_ * H_);   // 16 x 64
    attn_mma<<<attn_grid, 256, ATT_SMEM>>>();

    dim3 out_grid(D_ / 64, M_TOT / 128); // 16 x 64
    mma_gemm<<<out_grid, 256, MMA_SMEM>>>(Hh, Hl, woh, wol, out, 3);
}

// round 9
// speedup vs baseline: 1.7670x; 1.7670x over previous
#include <cuda_runtime.h>
#include <cuda_fp16.h>
#include <cstdint>

#define B_  4
#define S_  2048
#define D_  1024
#define H_  16
#define M_TOT 8192

// ---------------- device scratch (no allocs allowed) ----------------
__device__ __align__(256) __half g_qh[M_TOT * D_], g_ql[M_TOT * D_];
__device__ __align__(256) __half g_kh[M_TOT * D_], g_kl[M_TOT * D_];
__device__ __align__(256) __half g_vh[M_TOT * D_], g_vl[M_TOT * D_];
__device__ __align__(256) __half g_wqh[H_ * 64 * D_], g_wql[H_ * 64 * D_];
__device__ __align__(256) __half g_wkh[H_ * 64 * D_], g_wkl[H_ * 64 * D_];
__device__ __align__(256) __half g_wvh[H_ * 64 * D_], g_wvl[H_ * 64 * D_];
__device__ __align__(256) __half g_woh[D_ * D_],     g_wol[D_ * D_];
__device__ __align__(256) __half g_Qh[64 * S_ * 64],  g_Ql[64 * S_ * 64];   // [bh][s][dk] (pre-scaled)
__device__ __align__(256) __half g_Kh[64 * S_ * 64],  g_Kl[64 * S_ * 64];   // [bh][key][dk]
__device__ __align__(256) __half g_Vth[64 * 64 * S_], g_Vtl[64 * 64 * S_];  // [bh][dv][key]
__device__ __align__(256) __half g_Hh[M_TOT * D_];                          // hi only (one-sided out proj)

// ---------------- PTX helpers (baseline ISA: sm_80+) ----------------
__device__ __forceinline__ uint32_t smem_u32(const void* p) {
    uint32_t a;
    asm("{ .reg .u64 t; cvta.to.shared.u64 t, %1; cvt.u32.u64 %0, t; }"
        : "=r"(a) : "l"(p));
    return a;
}
__device__ __forceinline__ void cp16(uint32_t dst, const void* src) {
    asm volatile("cp.async.cg.shared.global [%0], [%1], 16;"
                 :: "r"(dst), "l"(src) : "memory");
}
#define CP_COMMIT() asm volatile("cp.async.commit_group;" ::: "memory")
#define CP_WAIT1()  asm volatile("cp.async.wait_group 1;"  ::: "memory")
#define CP_WAIT0()  asm volatile("cp.async.wait_group 0;"  ::: "memory")

__device__ __forceinline__ void ldsm_x4(uint32_t* r, uint32_t addr) {
    asm volatile("ldmatrix.sync.aligned.m8n8.x4.shared.b16 {%0,%1,%2,%3}, [%4];"
                 : "=r"(r[0]), "=r"(r[1]), "=r"(r[2]), "=r"(r[3]) : "r"(addr));
}
// fp16 inputs, fp32 accumulate (the fast legacy path — r8 proved f16-acc is slower)
__device__ __forceinline__ void hmma(float* d, const uint32_t* a,
                                     uint32_t b0, uint32_t b1) {
    asm volatile("mma.sync.aligned.m16n8k16.row.col.f32.f16.f16.f32 "
                 "{%0,%1,%2,%3}, {%4,%5,%6,%7}, {%8,%9}, {%0,%1,%2,%3};"
                 : "+f"(d[0]), "+f"(d[1]), "+f"(d[2]), "+f"(d[3])
                 : "r"(a[0]), "r"(a[1]), "r"(a[2]), "r"(a[3]), "r"(b0), "r"(b1));
}
__device__ __forceinline__ uint32_t swz(uint32_t off) {
    return off ^ ((off >> 3) & 0x70);
}
__device__ __forceinline__ void split_f16(float x, __half& h, __half& l) {
    h = __float2half_rn(x);
    l = __float2half_rn(x - __half2float(h));
}
__device__ __forceinline__ uint32_t packsplit(float x, float y, uint32_t& lo) {
    __half hx, hy, lx, ly;
    split_f16(x, hx, lx);
    split_f16(y, hy, ly);
    __half2 hv = __halves2half2(hx, hy);
    __half2 lv = __halves2half2(lx, ly);
    lo = *reinterpret_cast<uint32_t*>(&lv);
    return *reinterpret_cast<uint32_t*>(&hv);
}
__device__ __forceinline__ uint32_t pack2(float x, float y) {
    __half2 h = __floats2half2_rn(x, y);
    return *reinterpret_cast<uint32_t*>(&h);
}

// ---------------- conversion kernels (fused) ----------------
__global__ __launch_bounds__(256) void conv_in3(const float* __restrict__ q,
                                                const float* __restrict__ k,
                                                const float* __restrict__ v)
{
    const int which = blockIdx.y;
    const float* x = (which == 0) ? q : ((which == 1) ? k : v);
    __half* hi = (which == 0) ? g_qh : ((which == 1) ? g_kh : g_vh);
    __half* lo = (which == 0) ? g_ql : ((which == 1) ? g_kl : g_vl);
    size_t i = ((size_t)blockIdx.x * 256 + threadIdx.x) * 4;
    float4 vv = *reinterpret_cast<const float4*>(x + i);
    __half h0, h1, h2, h3, l0, l1, l2, l3;
    split_f16(vv.x, h0, l0); split_f16(vv.y, h1, l1);
    split_f16(vv.z, h2, l2); split_f16(vv.w, h3, l3);
    *reinterpret_cast<__half2*>(hi + i)     = __halves2half2(h0, h1);
    *reinterpret_cast<__half2*>(hi + i + 2) = __halves2half2(h2, h3);
    *reinterpret_cast<__half2*>(lo + i)     = __halves2half2(l0, l1);
    *reinterpret_cast<__half2*>(lo + i + 2) = __halves2half2(l2, l3);
}

// W[h][k][n] (16,1024,64) -> Wt[h][n][k] hi/lo, all three weights
__global__ __launch_bounds__(256) void conv_w3(const float* __restrict__ Wq,
                                               const float* __restrict__ Wk,
                                               const float* __restrict__ Wv)
{
    const int which = blockIdx.y;
    const float* W = (which == 0) ? Wq : ((which == 1) ? Wk : Wv);
    __half* hi = (which == 0) ? g_wqh : ((which == 1) ? g_wkh : g_wvh);
    __half* lo = (which == 0) ? g_wql : ((which == 1) ? g_wkl : g_wvl);
    int idx = blockIdx.x * 256 + threadIdx.x;        // h*65536 + n*1024 + k
    int k = idx & 1023;
    int n = (idx >> 10) & 63;
    int h = idx >> 16;
    float x = W[((size_t)h * D_ + k) * 64 + n];
    __half hh, ll;
    split_f16(x, hh, ll);
    hi[idx] = hh; lo[idx] = ll;
}

__global__ __launch_bounds__(256) void conv_wo(const float* __restrict__ Wo)
{
    int idx = blockIdx.x * 256 + threadIdx.x;        // n*1024 + k
    int k = idx & 1023;
    int n = idx >> 10;
    float x = Wo[(size_t)k * D_ + n];
    __half hh, ll;
    split_f16(x, hh, ll);
    g_woh[idx] = hh; g_wol[idx] = ll;
}

// ---------------- split-fp16 HMMA GEMM (256 thr, 8 warps x 16 rows) ----------------
// 3-term (score path: Q/K projections): Ah*Bh + Ah*Bl + Al*Bh   (f32 acc)
// 2-term (one-sided: V proj, out proj): Ah*Bh + Ah*Bl
// mode 3: out proj (fp32 out). mode 4: z-merged Q/K/V projections (z=0/1/2).
#define STAGE_BYTES 49152
#define A_HI_OFF 0
#define A_LO_OFF 16384
#define B_HI_OFF 32768
#define B_LO_OFF 40960
#define MMA_SMEM (2 * STAGE_BYTES)

__global__ __launch_bounds__(256) void mma_gemm(const __half* __restrict__ ah_,
                                                const __half* __restrict__ al_,
                                                const __half* __restrict__ bh_,
                                                const __half* __restrict__ bl_,
                                                float* __restrict__ outp, int mode)
{
    extern __shared__ char sm[];
    const uint32_t smem = smem_u32(sm);
    const int tid  = threadIdx.x;
    const int wid  = tid >> 5;
    const int lane = tid & 31;
    const int nb   = blockIdx.x;
    const int m0   = blockIdx.y * 128;
    const int mbase = wid * 16;

    int emode = mode;
    const __half *ah = ah_, *al = al_, *bh = bh_, *bl = bl_;
    if (mode == 4) {
        const int z = blockIdx.z;          // 0=Q 1=K 2=V
        emode = z;
        ah = (z == 0) ? g_qh : ((z == 1) ? g_kh : g_vh);
        al = (z == 0) ? g_ql : ((z == 1) ? g_kl : g_vl);
        bh = (z == 0) ? g_wqh : ((z == 1) ? g_wkh : g_wvh);
        bl = (z == 0) ? g_wql : ((z == 1) ? g_wkl : g_wvl);
    }
    const bool three = (emode <= 1);   // Q/K projections need the Al*Bh term

    const __half* aH = ah + (size_t)m0 * D_;
    const __half* aL = al + (size_t)m0 * D_;
    const __half* bH = bh + (size_t)nb * 64 * D_;
    const __half* bL = bl + (size_t)nb * 64 * D_;

    const int arow = tid >> 1, ahalf = tid & 1;
    const int brow_ = tid >> 2, bq = tid & 3;
    auto load_stage = [&](int c, int buf) {
        const uint32_t sb = smem + buf * STAGE_BYTES;
        const int k0 = c * 64;
        const char* gh = (const char*)(aH + (size_t)arow * D_ + k0) + ahalf * 64;
        const char* gl = (const char*)(aL + (size_t)arow * D_ + k0) + ahalf * 64;
        #pragma unroll
        for (int j = 0; j < 4; ++j) {
            uint32_t sw = swz(arow * 128 + ahalf * 64 + j * 16);
            cp16(sb + A_HI_OFF + sw, gh + j * 16);
            if (three) cp16(sb + A_LO_OFF + sw, gl + j * 16);
        }
        const char* gbh = (const char*)(bH + (size_t)brow_ * D_ + k0) + bq * 32;
        const char* gbl = (const char*)(bL + (size_t)brow_ * D_ + k0) + bq * 32;
        #pragma unroll
        for (int j = 0; j < 2; ++j) {
            uint32_t sw = swz(brow_ * 128 + bq * 32 + j * 16);
            cp16(sb + B_HI_OFF + sw, gbh + j * 16);
            cp16(sb + B_LO_OFF + sw, gbl + j * 16);
        }
    };

    float acc[8][4] = {};

    load_stage(0, 0);
    CP_COMMIT();

    for (int c = 0; c < 16; ++c) {
        const int buf = c & 1;
        if (c < 15) { load_stage(c + 1, buf ^ 1); CP_COMMIT(); }
        if (c < 15) CP_WAIT1(); else CP_WAIT0();
        __syncthreads();

        const uint32_t sb = smem + buf * STAGE_BYTES;
        #pragma unroll
        for (int ks = 0; ks < 4; ++ks) {
            const int kb = ks * 32;
            uint32_t ahi[4], alo[4];
            {
                uint32_t off = (uint32_t)(mbase + (lane & 15)) * 128
                             + kb + (lane >> 4) * 16;
                uint32_t sw = swz(off);
                ldsm_x4(ahi, sb + A_HI_OFF + sw);
                if (three) ldsm_x4(alo, sb + A_LO_OFF + sw);
            }
            uint32_t bhi[4][4], blo[4][4];
            #pragma unroll
            for (int np = 0; np < 4; ++np) {
                uint32_t n  = np * 16 + (lane & 7) + ((lane >> 4) << 3);
                uint32_t off = n * 128 + kb + ((lane >> 3) & 1) * 16;
                uint32_t sw = swz(off);
                ldsm_x4(bhi[np], sb + B_HI_OFF + sw);
                ldsm_x4(blo[np], sb + B_LO_OFF + sw);
            }
            #pragma unroll
            for (int nf = 0; nf < 8; ++nf) {
                const int np = nf >> 1, sel = (nf & 1) * 2;
                hmma(acc[nf], ahi, bhi[np][sel], bhi[np][sel + 1]);
            }
            #pragma unroll
            for (int nf = 0; nf < 8; ++nf) {
                const int np = nf >> 1, sel = (nf & 1) * 2;
                hmma(acc[nf], ahi, blo[np][sel], blo[np][sel + 1]);
            }
            if (three) {
                #pragma unroll
                for (int nf = 0; nf < 8; ++nf) {
                    const int np = nf >> 1, sel = (nf & 1) * 2;
                    hmma(acc[nf], alo, bhi[np][sel], bhi[np][sel + 1]);
                }
            }
        }
        __syncthreads();
    }

    // ---- epilogue ----
    const int g = lane >> 2;
    const int t = lane & 3;
    #pragma unroll
    for (int half = 0; half < 2; ++half) {
        const int m = m0 + mbase + half * 8 + g;
        if (emode == 3) {
            float* orow = outp + (size_t)m * D_ + nb * 64;
            #pragma unroll
            for (int nf = 0; nf < 8; ++nf)
                *reinterpret_cast<float2*>(orow + nf * 8 + t * 2) =
                    make_float2(acc[nf][half * 2], acc[nf][half * 2 + 1]);
        } else {
            const int b = m >> 11, s = m & (S_ - 1);
            const int bh_i = b * H_ + nb;
            if (emode < 2) {
                const float sc = (emode == 0) ? 0.125f : 1.0f;
                __half* dh = (emode == 0) ? g_Qh : g_Kh;
                __half* dl = (emode == 0) ? g_Ql : g_Kl;
                size_t base = ((size_t)bh_i * S_ + s) * 64;
                #pragma unroll
                for (int nf = 0; nf < 8; ++nf) {
                    uint32_t lo, hi = packsplit(acc[nf][half * 2] * sc,
                                                acc[nf][half * 2 + 1] * sc, lo);
                    *reinterpret_cast<uint32_t*>(dh + base + nf * 8 + t * 2) = hi;
                    *reinterpret_cast<uint32_t*>(dl + base + nf * 8 + t * 2) = lo;
                }
            } else {
                // V transpose: element (s=key, dv) -> [bh][dv][key], split hi/lo
                #pragma unroll
                for (int nf = 0; nf < 8; ++nf) {
                    #pragma unroll
                    for (int e = 0; e < 2; ++e) {
                        int dv = nf * 8 + t * 2 + e;
                        __half hh, ll;
                        split_f16(acc[nf][half * 2 + e], hh, ll);
                        size_t addr = ((size_t)bh_i * 64 + dv) * S_ + s;
                        g_Vth[addr] = hh;
                        g_Vtl[addr] = ll;
                    }
                }
            }
        }
    }
}

// ---------------- tensor-core flash attention (256 thr, 8 warps x 16 q-rows) ----------------
// QK^T: 3-term split (score precision). PV: 2-term one-sided (P rounded, V split).
#define KH_OFF 0
#define KL_OFF 8192
#define VH_OFF 16384
#define VL_OFF 24576
#define AT_STAGE 32768
#define QH_OFF 65536
#define QL_OFF (65536 + 16384)
#define ATT_SMEM 98304

__global__ __launch_bounds__(256) void attn_mma()
{
    extern __shared__ char sm[];
    const uint32_t smem = smem_u32(sm);
    const int tid  = threadIdx.x;
    const int wid  = tid >> 5;
    const int lane = tid & 31;
    const int bh   = blockIdx.y;
    const int q0   = blockIdx.x * 128;
    const int mbase = wid * 16;

    // Q tile async load
    {
        const int row = tid >> 1, half = tid & 1;
        const char* gh = (const char*)(g_Qh + ((size_t)bh * S_ + q0 + row) * 64) + half * 64;
        const char* gl = (const char*)(g_Ql + ((size_t)bh * S_ + q0 + row) * 64) + half * 64;
        #pragma unroll
        for (int i = 0; i < 4; ++i) {
            uint32_t sw = swz(row * 128 + half * 64 + i * 16);
            cp16(smem + QH_OFF + sw, gh + i * 16);
            cp16(smem + QL_OFF + sw, gl + i * 16);
        }
    }
    const int r4 = tid >> 2, qq = tid & 3;
    auto load_stage = [&](int kt, int buf) {
        const uint32_t sb = smem + buf * AT_STAGE;
        const char* kh = (const char*)(g_Kh + ((size_t)bh * S_ + kt + r4) * 64) + qq * 32;
        const char* kl = (const char*)(g_Kl + ((size_t)bh * S_ + kt + r4) * 64) + qq * 32;
        const char* vh = (const char*)(g_Vth + ((size_t)bh * 64 + r4) * S_ + kt) + qq * 32;
        const char* vl = (const char*)(g_Vtl + ((size_t)bh * 64 + r4) * S_ + kt) + qq * 32;
        #pragma unroll
        for (int j = 0; j < 2; ++j) {
            uint32_t sw = swz(r4 * 128 + qq * 32 + j * 16);
            cp16(sb + KH_OFF + sw, kh + j * 16);
            cp16(sb + KL_OFF + sw, kl + j * 16);
            cp16(sb + VH_OFF + sw, vh + j * 16);
            cp16(sb + VL_OFF + sw, vl + j * 16);
        }
    };
    load_stage(0, 0);  CP_COMMIT();
    load_stage(64, 1); CP_COMMIT();
    CP_WAIT1();
    __syncthreads();

    // persistent Q hi fragments; Q lo re-loaded per use
    uint32_t qh[4][4];
    #pragma unroll
    for (int ks = 0; ks < 4; ++ks) {
        uint32_t off = (uint32_t)(mbase + (lane & 15)) * 128
                     + ks * 32 + (lane >> 4) * 16;
        ldsm_x4(qh[ks], smem + QH_OFF + swz(off));
    }

    float O[8][4] = {};
    float mrow[2] = {-1e30f, -1e30f};
    float lrow[2] = {};

    for (int c = 0; c < 32; ++c) {
        const uint32_t sb = smem + (c & 1) * AT_STAGE;

        // ---- QK^T (3-term split, term-major in np-pairs) ----
        float s[8][4] = {};
        #pragma unroll
        for (int ks = 0; ks < 4; ++ks) {
            uint32_t ql_[4];
            {
                uint32_t off = (uint32_t)(mbase + (lane & 15)) * 128
                             + ks * 32 + (lane >> 4) * 16;
                ldsm_x4(ql_, smem + QL_OFF + swz(off));
            }
            #pragma unroll
            for (int np2 = 0; np2 < 2; ++np2) {
                uint32_t kbh2[2][4], kbl2[2][4];
                #pragma unroll
                for (int j = 0; j < 2; ++j) {
                    const int np = np2 * 2 + j;
                    uint32_t n  = np * 16 + (lane & 7) + ((lane >> 4) << 3);
                    uint32_t off = n * 128 + ks * 32 + ((lane >> 3) & 1) * 16;
                    uint32_t sw = swz(off);
                    ldsm_x4(kbh2[j], sb + KH_OFF + sw);
                    ldsm_x4(kbl2[j], sb + KL_OFF + sw);
                }
                #pragma unroll
                for (int j = 0; j < 4; ++j) {
                    const int p = j >> 1, sel = (j & 1) * 2;
                    hmma(s[np2 * 4 + j], qh[ks], kbh2[p][sel], kbh2[p][sel + 1]);
                }
                #pragma unroll
                for (int j = 0; j < 4; ++j) {
                    const int p = j >> 1, sel = (j & 1) * 2;
                    hmma(s[np2 * 4 + j], qh[ks], kbl2[p][sel], kbl2[p][sel + 1]);
                }
                #pragma unroll
                for (int j = 0; j < 4; ++j) {
                    const int p = j >> 1, sel = (j & 1) * 2;
                    hmma(s[np2 * 4 + j], ql_, kbh2[p][sel], kbh2[p][sel + 1]);
                }
            }
        }

        // ---- online softmax on fragments ----
        #pragma unroll
        for (int half = 0; half < 2; ++half) {
            float rmax = -1e30f;
            #pragma unroll
            for (int nf = 0; nf < 8; ++nf)
                rmax = fmaxf(rmax, fmaxf(s[nf][half * 2], s[nf][half * 2 + 1]));
            rmax = fmaxf(rmax, __shfl_xor_sync(0xffffffffu, rmax, 1));
            rmax = fmaxf(rmax, __shfl_xor_sync(0xffffffffu, rmax, 2));
            const float mnew = fmaxf(mrow[half], rmax);
            const float corr = __expf(mrow[half] - mnew);
            float rsum = 0.0f;
            #pragma unroll
            for (int nf = 0; nf < 8; ++nf) {
                float p0 = __expf(s[nf][half * 2]     - mnew);
                float p1 = __expf(s[nf][half * 2 + 1] - mnew);
                s[nf][half * 2]     = p0;
                s[nf][half * 2 + 1] = p1;
                rsum += p0 + p1;
            }
            rsum += __shfl_xor_sync(0xffffffffu, rsum, 1);
            rsum += __shfl_xor_sync(0xffffffffu, rsum, 2);
            lrow[half] = lrow[half] * corr + rsum;
            mrow[half] = mnew;
            #pragma unroll
            for (int nf = 0; nf < 8; ++nf) {
                O[nf][half * 2]     *= corr;
                O[nf][half * 2 + 1] *= corr;
            }
        }

        // ---- P @ V (2-term one-sided: P rounded fp16, V split hi/lo) ----
        #pragma unroll
        for (int kk = 0; kk < 4; ++kk) {
            uint32_t pah[4];
            pah[0] = pack2(s[2 * kk][0],     s[2 * kk][1]);
            pah[1] = pack2(s[2 * kk][2],     s[2 * kk][3]);
            pah[2] = pack2(s[2 * kk + 1][0], s[2 * kk + 1][1]);
            pah[3] = pack2(s[2 * kk + 1][2], s[2 * kk + 1][3]);
            #pragma unroll
            for (int np2 = 0; np2 < 2; ++np2) {
                uint32_t vbh2[2][4], vbl2[2][4];
                #pragma unroll
                for (int j = 0; j < 2; ++j) {
                    const int np = np2 * 2 + j;
                    uint32_t n  = np * 16 + (lane & 7) + ((lane >> 4) << 3);
                    uint32_t off = n * 128 + kk * 32 + ((lane >> 3) & 1) * 16;
                    uint32_t sw = swz(off);
                    ldsm_x4(vbh2[j], sb + VH_OFF + sw);
                    ldsm_x4(vbl2[j], sb + VL_OFF + sw);
                }
                #pragma unroll
                for (int j = 0; j < 4; ++j) {
                    const int p = j >> 1, sel = (j & 1) * 2;
                    hmma(O[np2 * 4 + j], pah, vbh2[p][sel], vbh2[p][sel + 1]);
                }
                #pragma unroll
                for (int j = 0; j < 4; ++j) {
                    const int p = j >> 1, sel = (j & 1) * 2;
                    hmma(O[np2 * 4 + j], pah, vbl2[p][sel], vbl2[p][sel + 1]);
                }
            }
        }

        __syncthreads();
        if (c + 2 < 32) {
            load_stage((c + 2) * 64, c & 1);
            CP_COMMIT();
            CP_WAIT1();
        } else if (c + 1 < 32) {
            CP_WAIT0();
        }
        __syncthreads();
    }

    // ---- epilogue: normalize, round to fp16 (hi only), concat-head layout ----
    const int b = bh >> 4, h = bh & 15;
    const int g = lane >> 2, t = lane & 3;
    #pragma unroll
    for (int half = 0; half < 2; ++half) {
        const float inv = 1.0f / lrow[half];
        const int srow = q0 + mbase + half * 8 + g;
        size_t base = ((size_t)(b * S_ + srow)) * D_ + h * 64;
        #pragma unroll
        for (int nf = 0; nf < 8; ++nf) {
            uint32_t hi = pack2(O[nf][half * 2] * inv, O[nf][half * 2 + 1] * inv);
            *reinterpret_cast<uint32_t*>(g_Hh + base + nf * 8 + t * 2) = hi;
        }
    }
}

// ---------------- launch ----------------
extern "C" void kernel_launch(void* const* d_in, const int* in_sizes, int n_in,
                              void* d_out, int out_size)
{
    const float* q  = (const float*)d_in[0];
    const float* k  = (const float*)d_in[1];
    const float* v  = (const float*)d_in[2];
    const float* Wq = (const float*)d_in[3];
    const float* Wk = (const float*)d_in[4];
    const float* Wv = (const float*)d_in[5];
    const float* Wo = (const float*)d_in[6];
    float* out = (float*)d_out;

    static bool configured = false;
    if (!configured) {
        cudaFuncSetAttribute(mma_gemm, cudaFuncAttributeMaxDynamicSharedMemorySize, MMA_SMEM);
        cudaFuncSetAttribute(attn_mma, cudaFuncAttributeMaxDynamicSharedMemorySize, ATT_SMEM);
        configured = true;
    }

    __half *woh, *wol, *Hh;
    cudaGetSymbolAddress((void**)&woh, g_woh); cudaGetSymbolAddress((void**)&wol, g_wol);
    cudaGetSymbolAddress((void**)&Hh, g_Hh);

    conv_in3<<<dim3(8192, 3), 256>>>(q, k, v);
    conv_w3<<<dim3(4096, 3), 256>>>(Wq, Wk, Wv);
    conv_wo<<<4096, 256>>>(Wo);

    // merged Q/K/V projections: one launch, z = which (Q/K 3-term, V 2-term)
    dim3 proj_grid(H_, M_TOT / 128, 3);
    mma_gemm<<<proj_grid, 256, MMA_SMEM>>>(nullptr, nullptr, nullptr, nullptr, nullptr, 4);

    dim3 attn_grid(S_ / 128, B_ * H_);   // 16 x 64
    attn_mma<<<attn_grid, 256, ATT_SMEM>>>();

    // out projection: one-sided 2-term (H hi only, Wo split)
    dim3 out_grid(D_ / 64, M_TOT / 128); // 16 x 64
    mma_gemm<<<out_grid, 256, MMA_SMEM>>>(Hh, Hh, woh, wol, out, 3);
}

// round 10
// speedup vs baseline: 1.9432x; 1.0997x over previous
#include <cuda_runtime.h>
#include <cuda_fp16.h>
#include <cstdint>

#define B_  4
#define S_  2048
#define D_  1024
#define H_  16
#define M_TOT 8192

// ---------------- device scratch (no allocs allowed) ----------------
__device__ __align__(256) __half g_qh[M_TOT * D_], g_ql[M_TOT * D_];
__device__ __align__(256) __half g_kh[M_TOT * D_], g_kl[M_TOT * D_];
__device__ __align__(256) __half g_vh[M_TOT * D_];
__device__ __align__(256) __half g_wqh[H_ * 64 * D_], g_wql[H_ * 64 * D_];
__device__ __align__(256) __half g_wkh[H_ * 64 * D_], g_wkl[H_ * 64 * D_];
__device__ __align__(256) __half g_wvh[H_ * 64 * D_];
__device__ __align__(256) __half g_woh[D_ * D_];
__device__ __align__(256) __half g_Qh[64 * S_ * 64];                        // [bh][s][dk] hi only (pre-scaled)
__device__ __align__(256) __half g_Kh[64 * S_ * 64],  g_Kl[64 * S_ * 64];   // [bh][key][dk]
__device__ __align__(256) __half g_Vth[64 * 64 * S_], g_Vtl[64 * 64 * S_];  // [bh][dv][key]
__device__ __align__(256) __half g_Hh[M_TOT * D_];                          // hi only

// ---------------- PTX helpers (baseline ISA: sm_80+) ----------------
__device__ __forceinline__ uint32_t smem_u32(const void* p) {
    uint32_t a;
    asm("{ .reg .u64 t; cvta.to.shared.u64 t, %1; cvt.u32.u64 %0, t; }"
        : "=r"(a) : "l"(p));
    return a;
}
__device__ __forceinline__ void cp16(uint32_t dst, const void* src) {
    asm volatile("cp.async.cg.shared.global [%0], [%1], 16;"
                 :: "r"(dst), "l"(src) : "memory");
}
#define CP_COMMIT() asm volatile("cp.async.commit_group;" ::: "memory")
#define CP_WAIT1()  asm volatile("cp.async.wait_group 1;"  ::: "memory")
#define CP_WAIT0()  asm volatile("cp.async.wait_group 0;"  ::: "memory")

__device__ __forceinline__ void ldsm_x4(uint32_t* r, uint32_t addr) {
    asm volatile("ldmatrix.sync.aligned.m8n8.x4.shared.b16 {%0,%1,%2,%3}, [%4];"
                 : "=r"(r[0]), "=r"(r[1]), "=r"(r[2]), "=r"(r[3]) : "r"(addr));
}
// fp16 inputs, fp32 accumulate (fastest legacy path per r7/r8 measurements)
__device__ __forceinline__ void hmma(float* d, const uint32_t* a,
                                     uint32_t b0, uint32_t b1) {
    asm volatile("mma.sync.aligned.m16n8k16.row.col.f32.f16.f16.f32 "
                 "{%0,%1,%2,%3}, {%4,%5,%6,%7}, {%8,%9}, {%0,%1,%2,%3};"
                 : "+f"(d[0]), "+f"(d[1]), "+f"(d[2]), "+f"(d[3])
                 : "r"(a[0]), "r"(a[1]), "r"(a[2]), "r"(a[3]), "r"(b0), "r"(b1));
}
__device__ __forceinline__ uint32_t swz(uint32_t off) {
    return off ^ ((off >> 3) & 0x70);
}
__device__ __forceinline__ void split_f16(float x, __half& h, __half& l) {
    h = __float2half_rn(x);
    l = __float2half_rn(x - __half2float(h));
}
__device__ __forceinline__ uint32_t packsplit(float x, float y, uint32_t& lo) {
    __half hx, hy, lx, ly;
    split_f16(x, hx, lx);
    split_f16(y, hy, ly);
    __half2 hv = __halves2half2(hx, hy);
    __half2 lv = __halves2half2(lx, ly);
    lo = *reinterpret_cast<uint32_t*>(&lv);
    return *reinterpret_cast<uint32_t*>(&hv);
}
__device__ __forceinline__ uint32_t pack2(float x, float y) {
    __half2 h = __floats2half2_rn(x, y);
    return *reinterpret_cast<uint32_t*>(&h);
}

// ---------------- conversion kernels (fused) ----------------
__global__ __launch_bounds__(256) void conv_in3(const float* __restrict__ q,
                                                const float* __restrict__ k,
                                                const float* __restrict__ v)
{
    const int which = blockIdx.y;
    const float* x = (which == 0) ? q : ((which == 1) ? k : v);
    __half* hi = (which == 0) ? g_qh : ((which == 1) ? g_kh : g_vh);
    __half* lo = (which == 0) ? g_ql : g_kl;   // V needs no lo (1-term proj)
    size_t i = ((size_t)blockIdx.x * 256 + threadIdx.x) * 4;
    float4 vv = *reinterpret_cast<const float4*>(x + i);
    __half h0, h1, h2, h3, l0, l1, l2, l3;
    split_f16(vv.x, h0, l0); split_f16(vv.y, h1, l1);
    split_f16(vv.z, h2, l2); split_f16(vv.w, h3, l3);
    *reinterpret_cast<__half2*>(hi + i)     = __halves2half2(h0, h1);
    *reinterpret_cast<__half2*>(hi + i + 2) = __halves2half2(h2, h3);
    if (which != 2) {
        *reinterpret_cast<__half2*>(lo + i)     = __halves2half2(l0, l1);
        *reinterpret_cast<__half2*>(lo + i + 2) = __halves2half2(l2, l3);
    }
}

// W[h][k][n] (16,1024,64) -> Wt[h][n][k] hi (and lo for Q/K)
__global__ __launch_bounds__(256) void conv_w3(const float* __restrict__ Wq,
                                               const float* __restrict__ Wk,
                                               const float* __restrict__ Wv)
{
    const int which = blockIdx.y;
    const float* W = (which == 0) ? Wq : ((which == 1) ? Wk : Wv);
    __half* hi = (which == 0) ? g_wqh : ((which == 1) ? g_wkh : g_wvh);
    __half* lo = (which == 0) ? g_wql : g_wkl;
    int idx = blockIdx.x * 256 + threadIdx.x;        // h*65536 + n*1024 + k
    int k = idx & 1023;
    int n = (idx >> 10) & 63;
    int h = idx >> 16;
    float x = W[((size_t)h * D_ + k) * 64 + n];
    __half hh, ll;
    split_f16(x, hh, ll);
    hi[idx] = hh;
    if (which != 2) lo[idx] = ll;
}

__global__ __launch_bounds__(256) void conv_wo(const float* __restrict__ Wo)
{
    int idx = blockIdx.x * 256 + threadIdx.x;        // n*1024 + k
    int k = idx & 1023;
    int n = idx >> 10;
    g_woh[idx] = __float2half_rn(Wo[(size_t)k * D_ + n]);
}

// ---------------- split-fp16 HMMA GEMM (256 thr, 8 warps x 16 rows) ----------------
// terms per mode: Q(0)=3, K(1)=3 (score path), V(2)=1, out(3)=1. f32 accumulate.
// mode 4: z-merged Q/K/V projections.
#define STAGE_BYTES 49152
#define A_HI_OFF 0
#define A_LO_OFF 16384
#define B_HI_OFF 32768
#define B_LO_OFF 40960
#define MMA_SMEM (2 * STAGE_BYTES)

__global__ __launch_bounds__(256) void mma_gemm(const __half* __restrict__ ah_,
                                                const __half* __restrict__ bh_,
                                                const __half* __restrict__ bl_,
                                                float* __restrict__ outp, int mode)
{
    extern __shared__ char sm[];
    const uint32_t smem = smem_u32(sm);
    const int tid  = threadIdx.x;
    const int wid  = tid >> 5;
    const int lane = tid & 31;
    const int nb   = blockIdx.x;
    const int m0   = blockIdx.y * 128;
    const int mbase = wid * 16;

    int emode = mode;
    const __half *ah = ah_, *al = nullptr, *bh = bh_, *bl = bl_;
    if (mode == 4) {
        const int z = blockIdx.z;          // 0=Q 1=K 2=V
        emode = z;
        ah = (z == 0) ? g_qh : ((z == 1) ? g_kh : g_vh);
        al = (z == 0) ? g_ql : g_kl;
        bh = (z == 0) ? g_wqh : ((z == 1) ? g_wkh : g_wvh);
        bl = (z == 0) ? g_wql : g_wkl;
    }
    const int nt = (emode <= 1) ? 3 : 1;   // Q/K: 3-term; V/out: 1-term

    const __half* aH = ah + (size_t)m0 * D_;
    const __half* aL = (nt >= 3) ? (al + (size_t)m0 * D_) : nullptr;
    const __half* bH = bh + (size_t)nb * 64 * D_;
    const __half* bL = (nt >= 2) ? (bl + (size_t)nb * 64 * D_) : nullptr;

    const int arow = tid >> 1, ahalf = tid & 1;
    const int brow_ = tid >> 2, bq = tid & 3;
    auto load_stage = [&](int c, int buf) {
        const uint32_t sb = smem + buf * STAGE_BYTES;
        const int k0 = c * 64;
        const char* gh = (const char*)(aH + (size_t)arow * D_ + k0) + ahalf * 64;
        #pragma unroll
        for (int j = 0; j < 4; ++j) {
            uint32_t sw = swz(arow * 128 + ahalf * 64 + j * 16);
            cp16(sb + A_HI_OFF + sw, gh + j * 16);
            if (nt >= 3) {
                const char* gl = (const char*)(aL + (size_t)arow * D_ + k0) + ahalf * 64;
                cp16(sb + A_LO_OFF + sw, gl + j * 16);
            }
        }
        const char* gbh = (const char*)(bH + (size_t)brow_ * D_ + k0) + bq * 32;
        #pragma unroll
        for (int j = 0; j < 2; ++j) {
            uint32_t sw = swz(brow_ * 128 + bq * 32 + j * 16);
            cp16(sb + B_HI_OFF + sw, gbh + j * 16);
            if (nt >= 2) {
                const char* gbl = (const char*)(bL + (size_t)brow_ * D_ + k0) + bq * 32;
                cp16(sb + B_LO_OFF + sw, gbl + j * 16);
            }
        }
    };

    float acc[8][4] = {};

    load_stage(0, 0);
    CP_COMMIT();

    for (int c = 0; c < 16; ++c) {
        const int buf = c & 1;
        if (c < 15) { load_stage(c + 1, buf ^ 1); CP_COMMIT(); }
        if (c < 15) CP_WAIT1(); else CP_WAIT0();
        __syncthreads();

        const uint32_t sb = smem + buf * STAGE_BYTES;
        #pragma unroll
        for (int ks = 0; ks < 4; ++ks) {
            const int kb = ks * 32;
            uint32_t ahi[4], alo[4];
            {
                uint32_t off = (uint32_t)(mbase + (lane & 15)) * 128
                             + kb + (lane >> 4) * 16;
                uint32_t sw = swz(off);
                ldsm_x4(ahi, sb + A_HI_OFF + sw);
                if (nt >= 3) ldsm_x4(alo, sb + A_LO_OFF + sw);
            }
            uint32_t bhi[4][4], blo[4][4];
            #pragma unroll
            for (int np = 0; np < 4; ++np) {
                uint32_t n  = np * 16 + (lane & 7) + ((lane >> 4) << 3);
                uint32_t off = n * 128 + kb + ((lane >> 3) & 1) * 16;
                uint32_t sw = swz(off);
                ldsm_x4(bhi[np], sb + B_HI_OFF + sw);
                if (nt >= 2) ldsm_x4(blo[np], sb + B_LO_OFF + sw);
            }
            #pragma unroll
            for (int nf = 0; nf < 8; ++nf) {
                const int np = nf >> 1, sel = (nf & 1) * 2;
                hmma(acc[nf], ahi, bhi[np][sel], bhi[np][sel + 1]);
            }
            if (nt >= 2) {
                #pragma unroll
                for (int nf = 0; nf < 8; ++nf) {
                    const int np = nf >> 1, sel = (nf & 1) * 2;
                    hmma(acc[nf], ahi, blo[np][sel], blo[np][sel + 1]);
                }
            }
            if (nt >= 3) {
                #pragma unroll
                for (int nf = 0; nf < 8; ++nf) {
                    const int np = nf >> 1, sel = (nf & 1) * 2;
                    hmma(acc[nf], alo, bhi[np][sel], bhi[np][sel + 1]);
                }
            }
        }
        __syncthreads();
    }

    // ---- epilogue ----
    const int g = lane >> 2;
    const int t = lane & 3;
    #pragma unroll
    for (int half = 0; half < 2; ++half) {
        const int m = m0 + mbase + half * 8 + g;
        if (emode == 3) {
            float* orow = outp + (size_t)m * D_ + nb * 64;
            #pragma unroll
            for (int nf = 0; nf < 8; ++nf)
                *reinterpret_cast<float2*>(orow + nf * 8 + t * 2) =
                    make_float2(acc[nf][half * 2], acc[nf][half * 2 + 1]);
        } else {
            const int b = m >> 11, s = m & (S_ - 1);
            const int bh_i = b * H_ + nb;
            if (emode == 0) {
                // Q: hi only, pre-scaled
                size_t base = ((size_t)bh_i * S_ + s) * 64;
                #pragma unroll
                for (int nf = 0; nf < 8; ++nf)
                    *reinterpret_cast<uint32_t*>(g_Qh + base + nf * 8 + t * 2) =
                        pack2(acc[nf][half * 2] * 0.125f, acc[nf][half * 2 + 1] * 0.125f);
            } else if (emode == 1) {
                size_t base = ((size_t)bh_i * S_ + s) * 64;
                #pragma unroll
                for (int nf = 0; nf < 8; ++nf) {
                    uint32_t lo, hi = packsplit(acc[nf][half * 2],
                                                acc[nf][half * 2 + 1], lo);
                    *reinterpret_cast<uint32_t*>(g_Kh + base + nf * 8 + t * 2) = hi;
                    *reinterpret_cast<uint32_t*>(g_Kl + base + nf * 8 + t * 2) = lo;
                }
            } else {
                // V transpose: (s=key, dv) -> [bh][dv][key], split hi/lo for 2-term PV
                #pragma unroll
                for (int nf = 0; nf < 8; ++nf) {
                    #pragma unroll
                    for (int e = 0; e < 2; ++e) {
                        int dv = nf * 8 + t * 2 + e;
                        __half hh, ll;
                        split_f16(acc[nf][half * 2 + e], hh, ll);
                        size_t addr = ((size_t)bh_i * 64 + dv) * S_ + s;
                        g_Vth[addr] = hh;
                        g_Vtl[addr] = ll;
                    }
                }
            }
        }
    }
}

// ---------------- tensor-core flash attention (256 thr, 8 warps x 16 q-rows) ----------------
// QK^T: 2-term (Qh*Kh + Qh*Kl). PV: 2-term (P rounded, V split hi/lo).
#define KH_OFF 0
#define KL_OFF 8192
#define VH_OFF 16384
#define VL_OFF 24576
#define AT_STAGE 32768
#define QH_OFF 65536
#define ATT_SMEM (65536 + 16384)

__global__ __launch_bounds__(256) void attn_mma()
{
    extern __shared__ char sm[];
    const uint32_t smem = smem_u32(sm);
    const int tid  = threadIdx.x;
    const int wid  = tid >> 5;
    const int lane = tid & 31;
    const int bh   = blockIdx.y;
    const int q0   = blockIdx.x * 128;
    const int mbase = wid * 16;

    // Q tile async load (hi only)
    {
        const int row = tid >> 1, half = tid & 1;
        const char* gh = (const char*)(g_Qh + ((size_t)bh * S_ + q0 + row) * 64) + half * 64;
        #pragma unroll
        for (int i = 0; i < 4; ++i) {
            uint32_t sw = swz(row * 128 + half * 64 + i * 16);
            cp16(smem + QH_OFF + sw, gh + i * 16);
        }
    }
    const int r4 = tid >> 2, qq = tid & 3;
    auto load_stage = [&](int kt, int buf) {
        const uint32_t sb = smem + buf * AT_STAGE;
        const char* kh = (const char*)(g_Kh + ((size_t)bh * S_ + kt + r4) * 64) + qq * 32;
        const char* kl = (const char*)(g_Kl + ((size_t)bh * S_ + kt + r4) * 64) + qq * 32;
        const char* vh = (const char*)(g_Vth + ((size_t)bh * 64 + r4) * S_ + kt) + qq * 32;
        const char* vl = (const char*)(g_Vtl + ((size_t)bh * 64 + r4) * S_ + kt) + qq * 32;
        #pragma unroll
        for (int j = 0; j < 2; ++j) {
            uint32_t sw = swz(r4 * 128 + qq * 32 + j * 16);
            cp16(sb + KH_OFF + sw, kh + j * 16);
            cp16(sb + KL_OFF + sw, kl + j * 16);
            cp16(sb + VH_OFF + sw, vh + j * 16);
            cp16(sb + VL_OFF + sw, vl + j * 16);
        }
    };
    load_stage(0, 0);  CP_COMMIT();
    load_stage(64, 1); CP_COMMIT();
    CP_WAIT1();
    __syncthreads();

    // persistent Q hi fragments
    uint32_t qh[4][4];
    #pragma unroll
    for (int ks = 0; ks < 4; ++ks) {
        uint32_t off = (uint32_t)(mbase + (lane & 15)) * 128
                     + ks * 32 + (lane >> 4) * 16;
        ldsm_x4(qh[ks], smem + QH_OFF + swz(off));
    }

    float O[8][4] = {};
    float mrow[2] = {-1e30f, -1e30f};
    float lrow[2] = {};

    for (int c = 0; c < 32; ++c) {
        const uint32_t sb = smem + (c & 1) * AT_STAGE;

        // ---- QK^T (2-term: Qh*Kh + Qh*Kl) ----
        float s[8][4] = {};
        #pragma unroll
        for (int ks = 0; ks < 4; ++ks) {
            #pragma unroll
            for (int np2 = 0; np2 < 2; ++np2) {
                uint32_t kbh2[2][4], kbl2[2][4];
                #pragma unroll
                for (int j = 0; j < 2; ++j) {
                    const int np = np2 * 2 + j;
                    uint32_t n  = np * 16 + (lane & 7) + ((lane >> 4) << 3);
                    uint32_t off = n * 128 + ks * 32 + ((lane >> 3) & 1) * 16;
                    uint32_t sw = swz(off);
                    ldsm_x4(kbh2[j], sb + KH_OFF + sw);
                    ldsm_x4(kbl2[j], sb + KL_OFF + sw);
                }
                #pragma unroll
                for (int j = 0; j < 4; ++j) {
                    const int p = j >> 1, sel = (j & 1) * 2;
                    hmma(s[np2 * 4 + j], qh[ks], kbh2[p][sel], kbh2[p][sel + 1]);
                }
                #pragma unroll
                for (int j = 0; j < 4; ++j) {
                    const int p = j >> 1, sel = (j & 1) * 2;
                    hmma(s[np2 * 4 + j], qh[ks], kbl2[p][sel], kbl2[p][sel + 1]);
                }
            }
        }

        // ---- online softmax (warp-uniform skip of rescale when max unchanged) ----
        #pragma unroll
        for (int half = 0; half < 2; ++half) {
            float rmax = -1e30f;
            #pragma unroll
            for (int nf = 0; nf < 8; ++nf)
                rmax = fmaxf(rmax, fmaxf(s[nf][half * 2], s[nf][half * 2 + 1]));
            rmax = fmaxf(rmax, __shfl_xor_sync(0xffffffffu, rmax, 1));
            rmax = fmaxf(rmax, __shfl_xor_sync(0xffffffffu, rmax, 2));
            if (__any_sync(0xffffffffu, rmax > mrow[half])) {
                const float mnew = fmaxf(mrow[half], rmax);
                const float corr = __expf(mrow[half] - mnew);
                lrow[half] *= corr;
                mrow[half] = mnew;
                #pragma unroll
                for (int nf = 0; nf < 8; ++nf) {
                    O[nf][half * 2]     *= corr;
                    O[nf][half * 2 + 1] *= corr;
                }
            }
            float rsum = 0.0f;
            #pragma unroll
            for (int nf = 0; nf < 8; ++nf) {
                float p0 = __expf(s[nf][half * 2]     - mrow[half]);
                float p1 = __expf(s[nf][half * 2 + 1] - mrow[half]);
                s[nf][half * 2]     = p0;
                s[nf][half * 2 + 1] = p1;
                rsum += p0 + p1;
            }
            rsum += __shfl_xor_sync(0xffffffffu, rsum, 1);
            rsum += __shfl_xor_sync(0xffffffffu, rsum, 2);
            lrow[half] += rsum;
        }

        // ---- P @ V (2-term: P rounded fp16, V split hi/lo) ----
        #pragma unroll
        for (int kk = 0; kk < 4; ++kk) {
            uint32_t pah[4];
            pah[0] = pack2(s[2 * kk][0],     s[2 * kk][1]);
            pah[1] = pack2(s[2 * kk][2],     s[2 * kk][3]);
            pah[2] = pack2(s[2 * kk + 1][0], s[2 * kk + 1][1]);
            pah[3] = pack2(s[2 * kk + 1][2], s[2 * kk + 1][3]);
            #pragma unroll
            for (int np2 = 0; np2 < 2; ++np2) {
                uint32_t vbh2[2][4], vbl2[2][4];
                #pragma unroll
                for (int j = 0; j < 2; ++j) {
                    const int np = np2 * 2 + j;
                    uint32_t n  = np * 16 + (lane & 7) + ((lane >> 4) << 3);
                    uint32_t off = n * 128 + kk * 32 + ((lane >> 3) & 1) * 16;
                    uint32_t sw = swz(off);
                    ldsm_x4(vbh2[j], sb + VH_OFF + sw);
                    ldsm_x4(vbl2[j], sb + VL_OFF + sw);
                }
                #pragma unroll
                for (int j = 0; j < 4; ++j) {
                    const int p = j >> 1, sel = (j & 1) * 2;
                    hmma(O[np2 * 4 + j], pah, vbh2[p][sel], vbh2[p][sel + 1]);
                }
                #pragma unroll
                for (int j = 0; j < 4; ++j) {
                    const int p = j >> 1, sel = (j & 1) * 2;
                    hmma(O[np2 * 4 + j], pah, vbl2[p][sel], vbl2[p][sel + 1]);
                }
            }
        }

        __syncthreads();
        if (c + 2 < 32) {
            load_stage((c + 2) * 64, c & 1);
            CP_COMMIT();
            CP_WAIT1();
        } else if (c + 1 < 32) {
            CP_WAIT0();
        }
        __syncthreads();
    }

    // ---- epilogue: normalize, round to fp16 hi, concat-head layout ----
    const int b = bh >> 4, h = bh & 15;
    const int g = lane >> 2, t = lane & 3;
    #pragma unroll
    for (int half = 0; half < 2; ++half) {
        const float inv = 1.0f / lrow[half];
        const int srow = q0 + mbase + half * 8 + g;
        size_t base = ((size_t)(b * S_ + srow)) * D_ + h * 64;
        #pragma unroll
        for (int nf = 0; nf < 8; ++nf) {
            uint32_t hi = pack2(O[nf][half * 2] * inv, O[nf][half * 2 + 1] * inv);
            *reinterpret_cast<uint32_t*>(g_Hh + base + nf * 8 + t * 2) = hi;
        }
    }
}

// ---------------- launch ----------------
extern "C" void kernel_launch(void* const* d_in, const int* in_sizes, int n_in,
                              void* d_out, int out_size)
{
    const float* q  = (const float*)d_in[0];
    const float* k  = (const float*)d_in[1];
    const float* v  = (const float*)d_in[2];
    const float* Wq = (const float*)d_in[3];
    const float* Wk = (const float*)d_in[4];
    const float* Wv = (const float*)d_in[5];
    const float* Wo = (const float*)d_in[6];
    float* out = (float*)d_out;

    static bool configured = false;
    if (!configured) {
        cudaFuncSetAttribute(mma_gemm, cudaFuncAttributeMaxDynamicSharedMemorySize, MMA_SMEM);
        cudaFuncSetAttribute(attn_mma, cudaFuncAttributeMaxDynamicSharedMemorySize, ATT_SMEM);
        configured = true;
    }

    __half *woh, *Hh;
    cudaGetSymbolAddress((void**)&woh, g_woh);
    cudaGetSymbolAddress((void**)&Hh, g_Hh);

    conv_in3<<<dim3(8192, 3), 256>>>(q, k, v);
    conv_w3<<<dim3(4096, 3), 256>>>(Wq, Wk, Wv);
    conv_wo<<<4096, 256>>>(Wo);

    // merged Q/K/V projections: one launch, z = which (Q/K 3-term, V 1-term)
    dim3 proj_grid(H_, M_TOT / 128, 3);
    mma_gemm<<<proj_grid, 256, MMA_SMEM>>>(nullptr, nullptr, nullptr, nullptr, 4);

    dim3 attn_grid(S_ / 128, B_ * H_);   // 16 x 64
    attn_mma<<<attn_grid, 256, ATT_SMEM>>>();

    // out projection: 1-term (H hi, Wo hi)
    dim3 out_grid(D_ / 64, M_TOT / 128); // 16 x 64
    mma_gemm<<<out_grid, 256, MMA_SMEM>>>(Hh, woh, nullptr, out, 3);
}

// round 11
// speedup vs baseline: 2.2419x; 1.1537x over previous
#include <cuda_runtime.h>
#include <cuda_fp16.h>
#include <cstdint>

#define B_  4
#define S_  2048
#define D_  1024
#define H_  16
#define M_TOT 8192

// ---------------- device scratch (no allocs allowed) ----------------
__device__ __align__(256) __half g_qh[M_TOT * D_], g_ql[M_TOT * D_];
__device__ __align__(256) __half g_kh[M_TOT * D_], g_kl[M_TOT * D_];
__device__ __align__(256) __half g_vh[M_TOT * D_];
__device__ __align__(256) __half g_wqh[H_ * 64 * D_], g_wql[H_ * 64 * D_];
__device__ __align__(256) __half g_wkh[H_ * 64 * D_], g_wkl[H_ * 64 * D_];
__device__ __align__(256) __half g_wvh[H_ * 64 * D_];
__device__ __align__(256) __half g_woh[D_ * D_];
__device__ __align__(256) __half g_Qh[64 * S_ * 64];                        // [bh][s][dk] hi only (pre-scaled)
__device__ __align__(256) __half g_Kh[64 * S_ * 64],  g_Kl[64 * S_ * 64];   // [bh][key][dk]
__device__ __align__(256) __half g_Vth[64 * 64 * S_];                       // [bh][dv][key] hi only
__device__ __align__(256) __half g_Hh[M_TOT * D_];                          // hi only

// ---------------- PTX helpers (baseline ISA: sm_80+) ----------------
__device__ __forceinline__ uint32_t smem_u32(const void* p) {
    uint32_t a;
    asm("{ .reg .u64 t; cvta.to.shared.u64 t, %1; cvt.u32.u64 %0, t; }"
        : "=r"(a) : "l"(p));
    return a;
}
__device__ __forceinline__ void cp16(uint32_t dst, const void* src) {
    asm volatile("cp.async.cg.shared.global [%0], [%1], 16;"
                 :: "r"(dst), "l"(src) : "memory");
}
#define CP_COMMIT() asm volatile("cp.async.commit_group;" ::: "memory")
#define CP_WAIT1()  asm volatile("cp.async.wait_group 1;"  ::: "memory")
#define CP_WAIT0()  asm volatile("cp.async.wait_group 0;"  ::: "memory")

__device__ __forceinline__ void ldsm_x4(uint32_t* r, uint32_t addr) {
    asm volatile("ldmatrix.sync.aligned.m8n8.x4.shared.b16 {%0,%1,%2,%3}, [%4];"
                 : "=r"(r[0]), "=r"(r[1]), "=r"(r[2]), "=r"(r[3]) : "r"(addr));
}
// fp16 inputs, fp32 accumulate (fastest legacy path per r7/r8 measurements)
__device__ __forceinline__ void hmma(float* d, const uint32_t* a,
                                     uint32_t b0, uint32_t b1) {
    asm volatile("mma.sync.aligned.m16n8k16.row.col.f32.f16.f16.f32 "
                 "{%0,%1,%2,%3}, {%4,%5,%6,%7}, {%8,%9}, {%0,%1,%2,%3};"
                 : "+f"(d[0]), "+f"(d[1]), "+f"(d[2]), "+f"(d[3])
                 : "r"(a[0]), "r"(a[1]), "r"(a[2]), "r"(a[3]), "r"(b0), "r"(b1));
}
__device__ __forceinline__ uint32_t swz(uint32_t off) {
    return off ^ ((off >> 3) & 0x70);
}
__device__ __forceinline__ void split_f16(float x, __half& h, __half& l) {
    h = __float2half_rn(x);
    l = __float2half_rn(x - __half2float(h));
}
__device__ __forceinline__ uint32_t packsplit(float x, float y, uint32_t& lo) {
    __half hx, hy, lx, ly;
    split_f16(x, hx, lx);
    split_f16(y, hy, ly);
    __half2 hv = __halves2half2(hx, hy);
    __half2 lv = __halves2half2(lx, ly);
    lo = *reinterpret_cast<uint32_t*>(&lv);
    return *reinterpret_cast<uint32_t*>(&hv);
}
__device__ __forceinline__ uint32_t pack2(float x, float y) {
    __half2 h = __floats2half2_rn(x, y);
    return *reinterpret_cast<uint32_t*>(&h);
}

// ---------------- conversion kernels (fused) ----------------
__global__ __launch_bounds__(256) void conv_in3(const float* __restrict__ q,
                                                const float* __restrict__ k,
                                                const float* __restrict__ v)
{
    const int which = blockIdx.y;
    const float* x = (which == 0) ? q : ((which == 1) ? k : v);
    __half* hi = (which == 0) ? g_qh : ((which == 1) ? g_kh : g_vh);
    __half* lo = (which == 0) ? g_ql : g_kl;   // V needs no lo (1-term proj)
    size_t i = ((size_t)blockIdx.x * 256 + threadIdx.x) * 4;
    float4 vv = *reinterpret_cast<const float4*>(x + i);
    __half h0, h1, h2, h3, l0, l1, l2, l3;
    split_f16(vv.x, h0, l0); split_f16(vv.y, h1, l1);
    split_f16(vv.z, h2, l2); split_f16(vv.w, h3, l3);
    *reinterpret_cast<__half2*>(hi + i)     = __halves2half2(h0, h1);
    *reinterpret_cast<__half2*>(hi + i + 2) = __halves2half2(h2, h3);
    if (which != 2) {
        *reinterpret_cast<__half2*>(lo + i)     = __halves2half2(l0, l1);
        *reinterpret_cast<__half2*>(lo + i + 2) = __halves2half2(l2, l3);
    }
}

// W[h][k][n] (16,1024,64) -> Wt[h][n][k] hi (and lo for Q/K)
__global__ __launch_bounds__(256) void conv_w3(const float* __restrict__ Wq,
                                               const float* __restrict__ Wk,
                                               const float* __restrict__ Wv)
{
    const int which = blockIdx.y;
    const float* W = (which == 0) ? Wq : ((which == 1) ? Wk : Wv);
    __half* hi = (which == 0) ? g_wqh : ((which == 1) ? g_wkh : g_wvh);
    __half* lo = (which == 0) ? g_wql : g_wkl;
    int idx = blockIdx.x * 256 + threadIdx.x;        // h*65536 + n*1024 + k
    int k = idx & 1023;
    int n = (idx >> 10) & 63;
    int h = idx >> 16;
    float x = W[((size_t)h * D_ + k) * 64 + n];
    __half hh, ll;
    split_f16(x, hh, ll);
    hi[idx] = hh;
    if (which != 2) lo[idx] = ll;
}

__global__ __launch_bounds__(256) void conv_wo(const float* __restrict__ Wo)
{
    int idx = blockIdx.x * 256 + threadIdx.x;        // n*1024 + k
    int k = idx & 1023;
    int n = idx >> 10;
    g_woh[idx] = __float2half_rn(Wo[(size_t)k * D_ + n]);
}

// ---------------- split-fp16 HMMA GEMM (256 thr, 8 warps x 16 rows) ----------------
// terms per mode: Q(0)=3, K(1)=3 (score path), V(2)=1, out(3)=1. f32 accumulate.
// mode 4: z-merged Q/K/V projections.
#define STAGE_BYTES 49152
#define A_HI_OFF 0
#define A_LO_OFF 16384
#define B_HI_OFF 32768
#define B_LO_OFF 40960
#define MMA_SMEM (2 * STAGE_BYTES)

__global__ __launch_bounds__(256) void mma_gemm(const __half* __restrict__ ah_,
                                                const __half* __restrict__ bh_,
                                                const __half* __restrict__ bl_,
                                                float* __restrict__ outp, int mode)
{
    extern __shared__ char sm[];
    const uint32_t smem = smem_u32(sm);
    const int tid  = threadIdx.x;
    const int wid  = tid >> 5;
    const int lane = tid & 31;
    const int nb   = blockIdx.x;
    const int m0   = blockIdx.y * 128;
    const int mbase = wid * 16;

    int emode = mode;
    const __half *ah = ah_, *al = nullptr, *bh = bh_, *bl = bl_;
    if (mode == 4) {
        const int z = blockIdx.z;          // 0=Q 1=K 2=V
        emode = z;
        ah = (z == 0) ? g_qh : ((z == 1) ? g_kh : g_vh);
        al = (z == 0) ? g_ql : g_kl;
        bh = (z == 0) ? g_wqh : ((z == 1) ? g_wkh : g_wvh);
        bl = (z == 0) ? g_wql : g_wkl;
    }
    const int nt = (emode <= 1) ? 3 : 1;   // Q/K: 3-term; V/out: 1-term

    const __half* aH = ah + (size_t)m0 * D_;
    const __half* aL = (nt >= 3) ? (al + (size_t)m0 * D_) : nullptr;
    const __half* bH = bh + (size_t)nb * 64 * D_;
    const __half* bL = (nt >= 2) ? (bl + (size_t)nb * 64 * D_) : nullptr;

    const int arow = tid >> 1, ahalf = tid & 1;
    const int brow_ = tid >> 2, bq = tid & 3;
    auto load_stage = [&](int c, int buf) {
        const uint32_t sb = smem + buf * STAGE_BYTES;
        const int k0 = c * 64;
        const char* gh = (const char*)(aH + (size_t)arow * D_ + k0) + ahalf * 64;
        #pragma unroll
        for (int j = 0; j < 4; ++j) {
            uint32_t sw = swz(arow * 128 + ahalf * 64 + j * 16);
            cp16(sb + A_HI_OFF + sw, gh + j * 16);
            if (nt >= 3) {
                const char* gl = (const char*)(aL + (size_t)arow * D_ + k0) + ahalf * 64;
                cp16(sb + A_LO_OFF + sw, gl + j * 16);
            }
        }
        const char* gbh = (const char*)(bH + (size_t)brow_ * D_ + k0) + bq * 32;
        #pragma unroll
        for (int j = 0; j < 2; ++j) {
            uint32_t sw = swz(brow_ * 128 + bq * 32 + j * 16);
            cp16(sb + B_HI_OFF + sw, gbh + j * 16);
            if (nt >= 2) {
                const char* gbl = (const char*)(bL + (size_t)brow_ * D_ + k0) + bq * 32;
                cp16(sb + B_LO_OFF + sw, gbl + j * 16);
            }
        }
    };

    float acc[8][4] = {};

    load_stage(0, 0);
    CP_COMMIT();

    for (int c = 0; c < 16; ++c) {
        const int buf = c & 1;
        if (c < 15) { load_stage(c + 1, buf ^ 1); CP_COMMIT(); }
        if (c < 15) CP_WAIT1(); else CP_WAIT0();
        __syncthreads();

        const uint32_t sb = smem + buf * STAGE_BYTES;
        #pragma unroll
        for (int ks = 0; ks < 4; ++ks) {
            const int kb = ks * 32;
            uint32_t ahi[4], alo[4];
            {
                uint32_t off = (uint32_t)(mbase + (lane & 15)) * 128
                             + kb + (lane >> 4) * 16;
                uint32_t sw = swz(off);
                ldsm_x4(ahi, sb + A_HI_OFF + sw);
                if (nt >= 3) ldsm_x4(alo, sb + A_LO_OFF + sw);
            }
            uint32_t bhi[4][4], blo[4][4];
            #pragma unroll
            for (int np = 0; np < 4; ++np) {
                uint32_t n  = np * 16 + (lane & 7) + ((lane >> 4) << 3);
                uint32_t off = n * 128 + kb + ((lane >> 3) & 1) * 16;
                uint32_t sw = swz(off);
                ldsm_x4(bhi[np], sb + B_HI_OFF + sw);
                if (nt >= 2) ldsm_x4(blo[np], sb + B_LO_OFF + sw);
            }
            #pragma unroll
            for (int nf = 0; nf < 8; ++nf) {
                const int np = nf >> 1, sel = (nf & 1) * 2;
                hmma(acc[nf], ahi, bhi[np][sel], bhi[np][sel + 1]);
            }
            if (nt >= 2) {
                #pragma unroll
                for (int nf = 0; nf < 8; ++nf) {
                    const int np = nf >> 1, sel = (nf & 1) * 2;
                    hmma(acc[nf], ahi, blo[np][sel], blo[np][sel + 1]);
                }
            }
            if (nt >= 3) {
                #pragma unroll
                for (int nf = 0; nf < 8; ++nf) {
                    const int np = nf >> 1, sel = (nf & 1) * 2;
                    hmma(acc[nf], alo, bhi[np][sel], bhi[np][sel + 1]);
                }
            }
        }
        __syncthreads();
    }

    // ---- epilogue ----
    const int g = lane >> 2;
    const int t = lane & 3;
    #pragma unroll
    for (int half = 0; half < 2; ++half) {
        const int m = m0 + mbase + half * 8 + g;
        if (emode == 3) {
            float* orow = outp + (size_t)m * D_ + nb * 64;
            #pragma unroll
            for (int nf = 0; nf < 8; ++nf)
                *reinterpret_cast<float2*>(orow + nf * 8 + t * 2) =
                    make_float2(acc[nf][half * 2], acc[nf][half * 2 + 1]);
        } else {
            const int b = m >> 11, s = m & (S_ - 1);
            const int bh_i = b * H_ + nb;
            if (emode == 0) {
                // Q: hi only, pre-scaled
                size_t base = ((size_t)bh_i * S_ + s) * 64;
                #pragma unroll
                for (int nf = 0; nf < 8; ++nf)
                    *reinterpret_cast<uint32_t*>(g_Qh + base + nf * 8 + t * 2) =
                        pack2(acc[nf][half * 2] * 0.125f, acc[nf][half * 2 + 1] * 0.125f);
            } else if (emode == 1) {
                size_t base = ((size_t)bh_i * S_ + s) * 64;
                #pragma unroll
                for (int nf = 0; nf < 8; ++nf) {
                    uint32_t lo, hi = packsplit(acc[nf][half * 2],
                                                acc[nf][half * 2 + 1], lo);
                    *reinterpret_cast<uint32_t*>(g_Kh + base + nf * 8 + t * 2) = hi;
                    *reinterpret_cast<uint32_t*>(g_Kl + base + nf * 8 + t * 2) = lo;
                }
            } else {
                // V transpose: (s=key, dv) -> [bh][dv][key], hi only (1-term PV)
                #pragma unroll
                for (int nf = 0; nf < 8; ++nf) {
                    #pragma unroll
                    for (int e = 0; e < 2; ++e) {
                        int dv = nf * 8 + t * 2 + e;
                        size_t addr = ((size_t)bh_i * 64 + dv) * S_ + s;
                        g_Vth[addr] = __float2half_rn(acc[nf][half * 2 + e]);
                    }
                }
            }
        }
    }
}

// ---------------- tensor-core flash attention (256 thr, 8 warps x 16 q-rows) ----------------
// QK^T: 2-term (Qh*Kh + Qh*Kl). PV: 1-term (P rounded fp16, V hi only).
#define KH_OFF 0
#define KL_OFF 8192
#define VH_OFF 16384
#define AT_STAGE 24576
#define QH_OFF (2 * AT_STAGE)
#define ATT_SMEM (QH_OFF + 16384)

__global__ __launch_bounds__(256) void attn_mma()
{
    extern __shared__ char sm[];
    const uint32_t smem = smem_u32(sm);
    const int tid  = threadIdx.x;
    const int wid  = tid >> 5;
    const int lane = tid & 31;
    const int bh   = blockIdx.y;
    const int q0   = blockIdx.x * 128;
    const int mbase = wid * 16;

    // Q tile async load (hi only)
    {
        const int row = tid >> 1, half = tid & 1;
        const char* gh = (const char*)(g_Qh + ((size_t)bh * S_ + q0 + row) * 64) + half * 64;
        #pragma unroll
        for (int i = 0; i < 4; ++i) {
            uint32_t sw = swz(row * 128 + half * 64 + i * 16);
            cp16(smem + QH_OFF + sw, gh + i * 16);
        }
    }
    const int r4 = tid >> 2, qq = tid & 3;
    auto load_stage = [&](int kt, int buf) {
        const uint32_t sb = smem + buf * AT_STAGE;
        const char* kh = (const char*)(g_Kh + ((size_t)bh * S_ + kt + r4) * 64) + qq * 32;
        const char* kl = (const char*)(g_Kl + ((size_t)bh * S_ + kt + r4) * 64) + qq * 32;
        const char* vh = (const char*)(g_Vth + ((size_t)bh * 64 + r4) * S_ + kt) + qq * 32;
        #pragma unroll
        for (int j = 0; j < 2; ++j) {
            uint32_t sw = swz(r4 * 128 + qq * 32 + j * 16);
            cp16(sb + KH_OFF + sw, kh + j * 16);
            cp16(sb + KL_OFF + sw, kl + j * 16);
            cp16(sb + VH_OFF + sw, vh + j * 16);
        }
    };
    load_stage(0, 0);  CP_COMMIT();
    load_stage(64, 1); CP_COMMIT();
    CP_WAIT1();
    __syncthreads();

    // persistent Q hi fragments
    uint32_t qh[4][4];
    #pragma unroll
    for (int ks = 0; ks < 4; ++ks) {
        uint32_t off = (uint32_t)(mbase + (lane & 15)) * 128
                     + ks * 32 + (lane >> 4) * 16;
        ldsm_x4(qh[ks], smem + QH_OFF + swz(off));
    }

    float O[8][4] = {};
    float mrow[2] = {-1e30f, -1e30f};
    float lrow[2] = {};

    for (int c = 0; c < 32; ++c) {
        const uint32_t sb = smem + (c & 1) * AT_STAGE;

        // ---- QK^T (2-term: Qh*Kh + Qh*Kl) ----
        float s[8][4] = {};
        #pragma unroll
        for (int ks = 0; ks < 4; ++ks) {
            #pragma unroll
            for (int np2 = 0; np2 < 2; ++np2) {
                uint32_t kbh2[2][4], kbl2[2][4];
                #pragma unroll
                for (int j = 0; j < 2; ++j) {
                    const int np = np2 * 2 + j;
                    uint32_t n  = np * 16 + (lane & 7) + ((lane >> 4) << 3);
                    uint32_t off = n * 128 + ks * 32 + ((lane >> 3) & 1) * 16;
                    uint32_t sw = swz(off);
                    ldsm_x4(kbh2[j], sb + KH_OFF + sw);
                    ldsm_x4(kbl2[j], sb + KL_OFF + sw);
                }
                #pragma unroll
                for (int j = 0; j < 4; ++j) {
                    const int p = j >> 1, sel = (j & 1) * 2;
                    hmma(s[np2 * 4 + j], qh[ks], kbh2[p][sel], kbh2[p][sel + 1]);
                }
                #pragma unroll
                for (int j = 0; j < 4; ++j) {
                    const int p = j >> 1, sel = (j & 1) * 2;
                    hmma(s[np2 * 4 + j], qh[ks], kbl2[p][sel], kbl2[p][sel + 1]);
                }
            }
        }

        // ---- online softmax (warp-uniform skip of rescale when max unchanged) ----
        #pragma unroll
        for (int half = 0; half < 2; ++half) {
            float rmax = -1e30f;
            #pragma unroll
            for (int nf = 0; nf < 8; ++nf)
                rmax = fmaxf(rmax, fmaxf(s[nf][half * 2], s[nf][half * 2 + 1]));
            rmax = fmaxf(rmax, __shfl_xor_sync(0xffffffffu, rmax, 1));
            rmax = fmaxf(rmax, __shfl_xor_sync(0xffffffffu, rmax, 2));
            if (__any_sync(0xffffffffu, rmax > mrow[half])) {
                const float mnew = fmaxf(mrow[half], rmax);
                const float corr = __expf(mrow[half] - mnew);
                lrow[half] *= corr;
                mrow[half] = mnew;
                #pragma unroll
                for (int nf = 0; nf < 8; ++nf) {
                    O[nf][half * 2]     *= corr;
                    O[nf][half * 2 + 1] *= corr;
                }
            }
            float rsum = 0.0f;
            #pragma unroll
            for (int nf = 0; nf < 8; ++nf) {
                float p0 = __expf(s[nf][half * 2]     - mrow[half]);
                float p1 = __expf(s[nf][half * 2 + 1] - mrow[half]);
                s[nf][half * 2]     = p0;
                s[nf][half * 2 + 1] = p1;
                rsum += p0 + p1;
            }
            rsum += __shfl_xor_sync(0xffffffffu, rsum, 1);
            rsum += __shfl_xor_sync(0xffffffffu, rsum, 2);
            lrow[half] += rsum;
        }

        // ---- P @ V (1-term: P rounded fp16, V hi) ----
        #pragma unroll
        for (int kk = 0; kk < 4; ++kk) {
            uint32_t pah[4];
            pah[0] = pack2(s[2 * kk][0],     s[2 * kk][1]);
            pah[1] = pack2(s[2 * kk][2],     s[2 * kk][3]);
            pah[2] = pack2(s[2 * kk + 1][0], s[2 * kk + 1][1]);
            pah[3] = pack2(s[2 * kk + 1][2], s[2 * kk + 1][3]);
            #pragma unroll
            for (int np2 = 0; np2 < 2; ++np2) {
                uint32_t vbh2[2][4];
                #pragma unroll
                for (int j = 0; j < 2; ++j) {
                    const int np = np2 * 2 + j;
                    uint32_t n  = np * 16 + (lane & 7) + ((lane >> 4) << 3);
                    uint32_t off = n * 128 + kk * 32 + ((lane >> 3) & 1) * 16;
                    ldsm_x4(vbh2[j], sb + VH_OFF + swz(off));
                }
                #pragma unroll
                for (int j = 0; j < 4; ++j) {
                    const int p = j >> 1, sel = (j & 1) * 2;
                    hmma(O[np2 * 4 + j], pah, vbh2[p][sel], vbh2[p][sel + 1]);
                }
            }
        }

        __syncthreads();
        if (c + 2 < 32) {
            load_stage((c + 2) * 64, c & 1);
            CP_COMMIT();
            CP_WAIT1();
        } else if (c + 1 < 32) {
            CP_WAIT0();
        }
        __syncthreads();
    }

    // ---- epilogue: normalize, round to fp16 hi, concat-head layout ----
    const int b = bh >> 4, h = bh & 15;
    const int g = lane >> 2, t = lane & 3;
    #pragma unroll
    for (int half = 0; half < 2; ++half) {
        const float inv = 1.0f / lrow[half];
        const int srow = q0 + mbase + half * 8 + g;
        size_t base = ((size_t)(b * S_ + srow)) * D_ + h * 64;
        #pragma unroll
        for (int nf = 0; nf < 8; ++nf) {
            uint32_t hi = pack2(O[nf][half * 2] * inv, O[nf][half * 2 + 1] * inv);
            *reinterpret_cast<uint32_t*>(g_Hh + base + nf * 8 + t * 2) = hi;
        }
    }
}

// ---------------- launch ----------------
extern "C" void kernel_launch(void* const* d_in, const int* in_sizes, int n_in,
                              void* d_out, int out_size)
{
    const float* q  = (const float*)d_in[0];
    const float* k  = (const float*)d_in[1];
    const float* v  = (const float*)d_in[2];
    const float* Wq = (const float*)d_in[3];
    const float* Wk = (const float*)d_in[4];
    const float* Wv = (const float*)d_in[5];
    const float* Wo = (const float*)d_in[6];
    float* out = (float*)d_out;

    static bool configured = false;
    if (!configured) {
        cudaFuncSetAttribute(mma_gemm, cudaFuncAttributeMaxDynamicSharedMemorySize, MMA_SMEM);
        cudaFuncSetAttribute(attn_mma, cudaFuncAttributeMaxDynamicSharedMemorySize, ATT_SMEM);
        configured = true;
    }

    __half *woh, *Hh;
    cudaGetSymbolAddress((void**)&woh, g_woh);
    cudaGetSymbolAddress((void**)&Hh, g_Hh);

    conv_in3<<<dim3(8192, 3), 256>>>(q, k, v);
    conv_w3<<<dim3(4096, 3), 256>>>(Wq, Wk, Wv);
    conv_wo<<<4096, 256>>>(Wo);

    // merged Q/K/V projections: one launch, z = which (Q/K 3-term, V 1-term)
    dim3 proj_grid(H_, M_TOT / 128, 3);
    mma_gemm<<<proj_grid, 256, MMA_SMEM>>>(nullptr, nullptr, nullptr, nullptr, 4);

    dim3 attn_grid(S_ / 128, B_ * H_);   // 16 x 64
    attn_mma<<<attn_grid, 256, ATT_SMEM>>>();

    // out projection: 1-term (H hi, Wo hi)
    dim3 out_grid(D_ / 64, M_TOT / 128); // 16 x 64
    mma_gemm<<<out_grid, 256, MMA_SMEM>>>(Hh, woh, nullptr, out, 3);
}

// round 12
// speedup vs baseline: 2.4661x; 1.1000x over previous
#include <cuda_runtime.h>
#include <cuda_fp16.h>
#include <cstdint>

#define B_  4
#define S_  2048
#define D_  1024
#define H_  16
#define M_TOT 8192

// ---------------- device scratch (no allocs allowed) ----------------
__device__ __align__(256) __half g_qh[M_TOT * D_], g_ql[M_TOT * D_];
__device__ __align__(256) __half g_kh[M_TOT * D_], g_kl[M_TOT * D_];
__device__ __align__(256) __half g_vh[M_TOT * D_];
__device__ __align__(256) __half g_wqh[H_ * 64 * D_], g_wql[H_ * 64 * D_];
__device__ __align__(256) __half g_wkh[H_ * 64 * D_], g_wkl[H_ * 64 * D_];
__device__ __align__(256) __half g_wvh[H_ * 64 * D_];
__device__ __align__(256) __half g_woh[D_ * D_];
__device__ __align__(256) __half g_Qh[64 * S_ * 64];     // [bh][s][dk] hi only (pre-scaled)
__device__ __align__(256) __half g_Kh[64 * S_ * 64];     // [bh][key][dk] hi only (3-term-accurate, rounded once)
__device__ __align__(256) __half g_Vth[64 * 64 * S_];    // [bh][dv][key] hi only
__device__ __align__(256) __half g_Hh[M_TOT * D_];       // hi only

// ---------------- PTX helpers (baseline ISA: sm_80+) ----------------
__device__ __forceinline__ uint32_t smem_u32(const void* p) {
    uint32_t a;
    asm("{ .reg .u64 t; cvta.to.shared.u64 t, %1; cvt.u32.u64 %0, t; }"
        : "=r"(a) : "l"(p));
    return a;
}
__device__ __forceinline__ void cp16(uint32_t dst, const void* src) {
    asm volatile("cp.async.cg.shared.global [%0], [%1], 16;"
                 :: "r"(dst), "l"(src) : "memory");
}
#define CP_COMMIT() asm volatile("cp.async.commit_group;" ::: "memory")
#define CP_WAIT1()  asm volatile("cp.async.wait_group 1;"  ::: "memory")
#define CP_WAIT0()  asm volatile("cp.async.wait_group 0;"  ::: "memory")

__device__ __forceinline__ void ldsm_x4(uint32_t* r, uint32_t addr) {
    asm volatile("ldmatrix.sync.aligned.m8n8.x4.shared.b16 {%0,%1,%2,%3}, [%4];"
                 : "=r"(r[0]), "=r"(r[1]), "=r"(r[2]), "=r"(r[3]) : "r"(addr));
}
// fp16 inputs, fp32 accumulate (fastest legacy path per r7/r8 measurements)
__device__ __forceinline__ void hmma(float* d, const uint32_t* a,
                                     uint32_t b0, uint32_t b1) {
    asm volatile("mma.sync.aligned.m16n8k16.row.col.f32.f16.f16.f32 "
                 "{%0,%1,%2,%3}, {%4,%5,%6,%7}, {%8,%9}, {%0,%1,%2,%3};"
                 : "+f"(d[0]), "+f"(d[1]), "+f"(d[2]), "+f"(d[3])
                 : "r"(a[0]), "r"(a[1]), "r"(a[2]), "r"(a[3]), "r"(b0), "r"(b1));
}
__device__ __forceinline__ uint32_t swz(uint32_t off) {
    return off ^ ((off >> 3) & 0x70);
}
__device__ __forceinline__ void split_f16(float x, __half& h, __half& l) {
    h = __float2half_rn(x);
    l = __float2half_rn(x - __half2float(h));
}
__device__ __forceinline__ uint32_t pack2(float x, float y) {
    __half2 h = __floats2half2_rn(x, y);
    return *reinterpret_cast<uint32_t*>(&h);
}

// ---------------- conversion kernels (fused) ----------------
__global__ __launch_bounds__(256) void conv_in3(const float* __restrict__ q,
                                                const float* __restrict__ k,
                                                const float* __restrict__ v)
{
    const int which = blockIdx.y;
    const float* x = (which == 0) ? q : ((which == 1) ? k : v);
    __half* hi = (which == 0) ? g_qh : ((which == 1) ? g_kh : g_vh);
    __half* lo = (which == 0) ? g_ql : g_kl;   // V needs no lo (1-term proj)
    size_t i = ((size_t)blockIdx.x * 256 + threadIdx.x) * 4;
    float4 vv = *reinterpret_cast<const float4*>(x + i);
    __half h0, h1, h2, h3, l0, l1, l2, l3;
    split_f16(vv.x, h0, l0); split_f16(vv.y, h1, l1);
    split_f16(vv.z, h2, l2); split_f16(vv.w, h3, l3);
    *reinterpret_cast<__half2*>(hi + i)     = __halves2half2(h0, h1);
    *reinterpret_cast<__half2*>(hi + i + 2) = __halves2half2(h2, h3);
    if (which != 2) {
        *reinterpret_cast<__half2*>(lo + i)     = __halves2half2(l0, l1);
        *reinterpret_cast<__half2*>(lo + i + 2) = __halves2half2(l2, l3);
    }
}

// W[h][k][n] (16,1024,64) -> Wt[h][n][k] hi (and lo for Q/K)
__global__ __launch_bounds__(256) void conv_w3(const float* __restrict__ Wq,
                                               const float* __restrict__ Wk,
                                               const float* __restrict__ Wv)
{
    const int which = blockIdx.y;
    const float* W = (which == 0) ? Wq : ((which == 1) ? Wk : Wv);
    __half* hi = (which == 0) ? g_wqh : ((which == 1) ? g_wkh : g_wvh);
    __half* lo = (which == 0) ? g_wql : g_wkl;
    int idx = blockIdx.x * 256 + threadIdx.x;        // h*65536 + n*1024 + k
    int k = idx & 1023;
    int n = (idx >> 10) & 63;
    int h = idx >> 16;
    float x = W[((size_t)h * D_ + k) * 64 + n];
    __half hh, ll;
    split_f16(x, hh, ll);
    hi[idx] = hh;
    if (which != 2) lo[idx] = ll;
}

__global__ __launch_bounds__(256) void conv_wo(const float* __restrict__ Wo)
{
    int idx = blockIdx.x * 256 + threadIdx.x;        // n*1024 + k
    int k = idx & 1023;
    int n = idx >> 10;
    g_woh[idx] = __float2half_rn(Wo[(size_t)k * D_ + n]);
}

// ---------------- split-fp16 HMMA GEMM (256 thr, 8 warps x 16 rows) ----------------
// terms per mode: Q(0)=3, K(1)=3 (accurate then rounded once), V(2)=1, out(3)=1.
// mode 4: z-merged Q/K/V projections.
#define STAGE_BYTES 49152
#define A_HI_OFF 0
#define A_LO_OFF 16384
#define B_HI_OFF 32768
#define B_LO_OFF 40960
#define MMA_SMEM (2 * STAGE_BYTES)

__global__ __launch_bounds__(256) void mma_gemm(const __half* __restrict__ ah_,
                                                const __half* __restrict__ bh_,
                                                const __half* __restrict__ bl_,
                                                float* __restrict__ outp, int mode)
{
    extern __shared__ char sm[];
    const uint32_t smem = smem_u32(sm);
    const int tid  = threadIdx.x;
    const int wid  = tid >> 5;
    const int lane = tid & 31;
    const int nb   = blockIdx.x;
    const int m0   = blockIdx.y * 128;
    const int mbase = wid * 16;

    int emode = mode;
    const __half *ah = ah_, *al = nullptr, *bh = bh_, *bl = bl_;
    if (mode == 4) {
        const int z = blockIdx.z;          // 0=Q 1=K 2=V
        emode = z;
        ah = (z == 0) ? g_qh : ((z == 1) ? g_kh : g_vh);
        al = (z == 0) ? g_ql : g_kl;
        bh = (z == 0) ? g_wqh : ((z == 1) ? g_wkh : g_wvh);
        bl = (z == 0) ? g_wql : g_wkl;
    }
    const int nt = (emode <= 1) ? 3 : 1;   // Q/K: 3-term; V/out: 1-term

    const __half* aH = ah + (size_t)m0 * D_;
    const __half* aL = (nt >= 3) ? (al + (size_t)m0 * D_) : nullptr;
    const __half* bH = bh + (size_t)nb * 64 * D_;
    const __half* bL = (nt >= 2) ? (bl + (size_t)nb * 64 * D_) : nullptr;

    const int arow = tid >> 1, ahalf = tid & 1;
    const int brow_ = tid >> 2, bq = tid & 3;
    auto load_stage = [&](int c, int buf) {
        const uint32_t sb = smem + buf * STAGE_BYTES;
        const int k0 = c * 64;
        const char* gh = (const char*)(aH + (size_t)arow * D_ + k0) + ahalf * 64;
        #pragma unroll
        for (int j = 0; j < 4; ++j) {
            uint32_t sw = swz(arow * 128 + ahalf * 64 + j * 16);
            cp16(sb + A_HI_OFF + sw, gh + j * 16);
            if (nt >= 3) {
                const char* gl = (const char*)(aL + (size_t)arow * D_ + k0) + ahalf * 64;
                cp16(sb + A_LO_OFF + sw, gl + j * 16);
            }
        }
        const char* gbh = (const char*)(bH + (size_t)brow_ * D_ + k0) + bq * 32;
        #pragma unroll
        for (int j = 0; j < 2; ++j) {
            uint32_t sw = swz(brow_ * 128 + bq * 32 + j * 16);
            cp16(sb + B_HI_OFF + sw, gbh + j * 16);
            if (nt >= 2) {
                const char* gbl = (const char*)(bL + (size_t)brow_ * D_ + k0) + bq * 32;
                cp16(sb + B_LO_OFF + sw, gbl + j * 16);
            }
        }
    };

    float acc[8][4] = {};

    load_stage(0, 0);
    CP_COMMIT();

    for (int c = 0; c < 16; ++c) {
        const int buf = c & 1;
        if (c < 15) { load_stage(c + 1, buf ^ 1); CP_COMMIT(); }
        if (c < 15) CP_WAIT1(); else CP_WAIT0();
        __syncthreads();

        const uint32_t sb = smem + buf * STAGE_BYTES;
        #pragma unroll
        for (int ks = 0; ks < 4; ++ks) {
            const int kb = ks * 32;
            uint32_t ahi[4], alo[4];
            {
                uint32_t off = (uint32_t)(mbase + (lane & 15)) * 128
                             + kb + (lane >> 4) * 16;
                uint32_t sw = swz(off);
                ldsm_x4(ahi, sb + A_HI_OFF + sw);
                if (nt >= 3) ldsm_x4(alo, sb + A_LO_OFF + sw);
            }
            uint32_t bhi[4][4], blo[4][4];
            #pragma unroll
            for (int np = 0; np < 4; ++np) {
                uint32_t n  = np * 16 + (lane & 7) + ((lane >> 4) << 3);
                uint32_t off = n * 128 + kb + ((lane >> 3) & 1) * 16;
                uint32_t sw = swz(off);
                ldsm_x4(bhi[np], sb + B_HI_OFF + sw);
                if (nt >= 2) ldsm_x4(blo[np], sb + B_LO_OFF + sw);
            }
            #pragma unroll
            for (int nf = 0; nf < 8; ++nf) {
                const int np = nf >> 1, sel = (nf & 1) * 2;
                hmma(acc[nf], ahi, bhi[np][sel], bhi[np][sel + 1]);
            }
            if (nt >= 2) {
                #pragma unroll
                for (int nf = 0; nf < 8; ++nf) {
                    const int np = nf >> 1, sel = (nf & 1) * 2;
                    hmma(acc[nf], ahi, blo[np][sel], blo[np][sel + 1]);
                }
            }
            if (nt >= 3) {
                #pragma unroll
                for (int nf = 0; nf < 8; ++nf) {
                    const int np = nf >> 1, sel = (nf & 1) * 2;
                    hmma(acc[nf], alo, bhi[np][sel], bhi[np][sel + 1]);
                }
            }
        }
        __syncthreads();
    }

    // ---- epilogue ----
    const int g = lane >> 2;
    const int t = lane & 3;
    #pragma unroll
    for (int half = 0; half < 2; ++half) {
        const int m = m0 + mbase + half * 8 + g;
        if (emode == 3) {
            float* orow = outp + (size_t)m * D_ + nb * 64;
            #pragma unroll
            for (int nf = 0; nf < 8; ++nf)
                *reinterpret_cast<float2*>(orow + nf * 8 + t * 2) =
                    make_float2(acc[nf][half * 2], acc[nf][half * 2 + 1]);
        } else {
            const int b = m >> 11, s = m & (S_ - 1);
            const int bh_i = b * H_ + nb;
            if (emode == 0) {
                // Q: hi only, pre-scaled
                size_t base = ((size_t)bh_i * S_ + s) * 64;
                #pragma unroll
                for (int nf = 0; nf < 8; ++nf)
                    *reinterpret_cast<uint32_t*>(g_Qh + base + nf * 8 + t * 2) =
                        pack2(acc[nf][half * 2] * 0.125f, acc[nf][half * 2 + 1] * 0.125f);
            } else if (emode == 1) {
                // K: hi only (rounded once from accurate 3-term f32)
                size_t base = ((size_t)bh_i * S_ + s) * 64;
                #pragma unroll
                for (int nf = 0; nf < 8; ++nf)
                    *reinterpret_cast<uint32_t*>(g_Kh + base + nf * 8 + t * 2) =
                        pack2(acc[nf][half * 2], acc[nf][half * 2 + 1]);
            } else {
                // V transpose: (s=key, dv) -> [bh][dv][key], hi only
                #pragma unroll
                for (int nf = 0; nf < 8; ++nf) {
                    #pragma unroll
                    for (int e = 0; e < 2; ++e) {
                        int dv = nf * 8 + t * 2 + e;
                        size_t addr = ((size_t)bh_i * 64 + dv) * S_ + s;
                        g_Vth[addr] = __float2half_rn(acc[nf][half * 2 + e]);
                    }
                }
            }
        }
    }
}

// ---------------- tensor-core flash attention (256 thr, 8 warps x 16 q-rows) ----------------
// QK^T: 1-term (Qh*Kh). PV: 1-term (P rounded fp16, V hi).
#define KH_OFF 0
#define VH_OFF 8192
#define AT_STAGE 16384
#define QH_OFF (2 * AT_STAGE)
#define ATT_SMEM (QH_OFF + 16384)

__global__ __launch_bounds__(256) void attn_mma()
{
    extern __shared__ char sm[];
    const uint32_t smem = smem_u32(sm);
    const int tid  = threadIdx.x;
    const int wid  = tid >> 5;
    const int lane = tid & 31;
    const int bh   = blockIdx.y;
    const int q0   = blockIdx.x * 128;
    const int mbase = wid * 16;

    // Q tile async load (hi only)
    {
        const int row = tid >> 1, half = tid & 1;
        const char* gh = (const char*)(g_Qh + ((size_t)bh * S_ + q0 + row) * 64) + half * 64;
        #pragma unroll
        for (int i = 0; i < 4; ++i) {
            uint32_t sw = swz(row * 128 + half * 64 + i * 16);
            cp16(smem + QH_OFF + sw, gh + i * 16);
        }
    }
    const int r4 = tid >> 2, qq = tid & 3;
    auto load_stage = [&](int kt, int buf) {
        const uint32_t sb = smem + buf * AT_STAGE;
        const char* kh = (const char*)(g_Kh + ((size_t)bh * S_ + kt + r4) * 64) + qq * 32;
        const char* vh = (const char*)(g_Vth + ((size_t)bh * 64 + r4) * S_ + kt) + qq * 32;
        #pragma unroll
        for (int j = 0; j < 2; ++j) {
            uint32_t sw = swz(r4 * 128 + qq * 32 + j * 16);
            cp16(sb + KH_OFF + sw, kh + j * 16);
            cp16(sb + VH_OFF + sw, vh + j * 16);
        }
    };
    load_stage(0, 0);  CP_COMMIT();
    load_stage(64, 1); CP_COMMIT();
    CP_WAIT1();
    __syncthreads();

    // persistent Q hi fragments
    uint32_t qh[4][4];
    #pragma unroll
    for (int ks = 0; ks < 4; ++ks) {
        uint32_t off = (uint32_t)(mbase + (lane & 15)) * 128
                     + ks * 32 + (lane >> 4) * 16;
        ldsm_x4(qh[ks], smem + QH_OFF + swz(off));
    }

    float O[8][4] = {};
    float mrow[2] = {-1e30f, -1e30f};
    float lrow[2] = {};

    for (int c = 0; c < 32; ++c) {
        const uint32_t sb = smem + (c & 1) * AT_STAGE;

        // ---- QK^T (1-term: Qh*Kh) ----
        float s[8][4] = {};
        #pragma unroll
        for (int ks = 0; ks < 4; ++ks) {
            #pragma unroll
            for (int np2 = 0; np2 < 2; ++np2) {
                uint32_t kbh2[2][4];
                #pragma unroll
                for (int j = 0; j < 2; ++j) {
                    const int np = np2 * 2 + j;
                    uint32_t n  = np * 16 + (lane & 7) + ((lane >> 4) << 3);
                    uint32_t off = n * 128 + ks * 32 + ((lane >> 3) & 1) * 16;
                    ldsm_x4(kbh2[j], sb + KH_OFF + swz(off));
                }
                #pragma unroll
                for (int j = 0; j < 4; ++j) {
                    const int p = j >> 1, sel = (j & 1) * 2;
                    hmma(s[np2 * 4 + j], qh[ks], kbh2[p][sel], kbh2[p][sel + 1]);
                }
            }
        }

        // ---- online softmax (warp-uniform skip of rescale when max unchanged) ----
        #pragma unroll
        for (int half = 0; half < 2; ++half) {
            float rmax = -1e30f;
            #pragma unroll
            for (int nf = 0; nf < 8; ++nf)
                rmax = fmaxf(rmax, fmaxf(s[nf][half * 2], s[nf][half * 2 + 1]));
            rmax = fmaxf(rmax, __shfl_xor_sync(0xffffffffu, rmax, 1));
            rmax = fmaxf(rmax, __shfl_xor_sync(0xffffffffu, rmax, 2));
            if (__any_sync(0xffffffffu, rmax > mrow[half])) {
                const float mnew = fmaxf(mrow[half], rmax);
                const float corr = __expf(mrow[half] - mnew);
                lrow[half] *= corr;
                mrow[half] = mnew;
                #pragma unroll
                for (int nf = 0; nf < 8; ++nf) {
                    O[nf][half * 2]     *= corr;
                    O[nf][half * 2 + 1] *= corr;
                }
            }
            float rsum = 0.0f;
            #pragma unroll
            for (int nf = 0; nf < 8; ++nf) {
                float p0 = __expf(s[nf][half * 2]     - mrow[half]);
                float p1 = __expf(s[nf][half * 2 + 1] - mrow[half]);
                s[nf][half * 2]     = p0;
                s[nf][half * 2 + 1] = p1;
                rsum += p0 + p1;
            }
            rsum += __shfl_xor_sync(0xffffffffu, rsum, 1);
            rsum += __shfl_xor_sync(0xffffffffu, rsum, 2);
            lrow[half] += rsum;
        }

        // ---- P @ V (1-term: P rounded fp16, V hi) ----
        #pragma unroll
        for (int kk = 0; kk < 4; ++kk) {
            uint32_t pah[4];
            pah[0] = pack2(s[2 * kk][0],     s[2 * kk][1]);
            pah[1] = pack2(s[2 * kk][2],     s[2 * kk][3]);
            pah[2] = pack2(s[2 * kk + 1][0], s[2 * kk + 1][1]);
            pah[3] = pack2(s[2 * kk + 1][2], s[2 * kk + 1][3]);
            #pragma unroll
            for (int np2 = 0; np2 < 2; ++np2) {
                uint32_t vbh2[2][4];
                #pragma unroll
                for (int j = 0; j < 2; ++j) {
                    const int np = np2 * 2 + j;
                    uint32_t n  = np * 16 + (lane & 7) + ((lane >> 4) << 3);
                    uint32_t off = n * 128 + kk * 32 + ((lane >> 3) & 1) * 16;
                    ldsm_x4(vbh2[j], sb + VH_OFF + swz(off));
                }
                #pragma unroll
                for (int j = 0; j < 4; ++j) {
                    const int p = j >> 1, sel = (j & 1) * 2;
                    hmma(O[np2 * 4 + j], pah, vbh2[p][sel], vbh2[p][sel + 1]);
                }
            }
        }

        __syncthreads();
        if (c + 2 < 32) {
            load_stage((c + 2) * 64, c & 1);
            CP_COMMIT();
            CP_WAIT1();
        } else if (c + 1 < 32) {
            CP_WAIT0();
        }
        __syncthreads();
    }

    // ---- epilogue: normalize, round to fp16 hi, concat-head layout ----
    const int b = bh >> 4, h = bh & 15;
    const int g = lane >> 2, t = lane & 3;
    #pragma unroll
    for (int half = 0; half < 2; ++half) {
        const float inv = 1.0f / lrow[half];
        const int srow = q0 + mbase + half * 8 + g;
        size_t base = ((size_t)(b * S_ + srow)) * D_ + h * 64;
        #pragma unroll
        for (int nf = 0; nf < 8; ++nf) {
            uint32_t hi = pack2(O[nf][half * 2] * inv, O[nf][half * 2 + 1] * inv);
            *reinterpret_cast<uint32_t*>(g_Hh + base + nf * 8 + t * 2) = hi;
        }
    }
}

// ---------------- launch ----------------
extern "C" void kernel_launch(void* const* d_in, const int* in_sizes, int n_in,
                              void* d_out, int out_size)
{
    const float* q  = (const float*)d_in[0];
    const float* k  = (const float*)d_in[1];
    const float* v  = (const float*)d_in[2];
    const float* Wq = (const float*)d_in[3];
    const float* Wk = (const float*)d_in[4];
    const float* Wv = (const float*)d_in[5];
    const float* Wo = (const float*)d_in[6];
    float* out = (float*)d_out;

    static bool configured = false;
    if (!configured) {
        cudaFuncSetAttribute(mma_gemm, cudaFuncAttributeMaxDynamicSharedMemorySize, MMA_SMEM);
        cudaFuncSetAttribute(attn_mma, cudaFuncAttributeMaxDynamicSharedMemorySize, ATT_SMEM);
        configured = true;
    }

    __half *woh, *Hh;
    cudaGetSymbolAddress((void**)&woh, g_woh);
    cudaGetSymbolAddress((void**)&Hh, g_Hh);

    conv_in3<<<dim3(8192, 3), 256>>>(q, k, v);
    conv_w3<<<dim3(4096, 3), 256>>>(Wq, Wk, Wv);
    conv_wo<<<4096, 256>>>(Wo);

    // merged Q/K/V projections: one launch, z = which (Q/K 3-term, V 1-term)
    dim3 proj_grid(H_, M_TOT / 128, 3);
    mma_gemm<<<proj_grid, 256, MMA_SMEM>>>(nullptr, nullptr, nullptr, nullptr, 4);

    dim3 attn_grid(S_ / 128, B_ * H_);   // 16 x 64
    attn_mma<<<attn_grid, 256, ATT_SMEM>>>();

    // out projection: 1-term (H hi, Wo hi)
    dim3 out_grid(D_ / 64, M_TOT / 128); // 16 x 64
    mma_gemm<<<out_grid, 256, MMA_SMEM>>>(Hh, woh, nullptr, out, 3);
}